// round 1
// baseline (speedup 1.0000x reference)
#include <cuda_runtime.h>
#include <math.h>

#define D_MODEL 1024
#define SEQ 2048
#define BATCH 2
#define NHEAD 16
#define HD 64
#define ROWS (BATCH*SEQ)   // 4096

// ---------------- scratch (static device memory; no allocation) ----------------
__device__ float g_XN[ROWS * D_MODEL];        // ln1(x)
__device__ float g_QKV[ROWS * 3 * D_MODEL];   // qkv
__device__ float g_O[ROWS * D_MODEL];         // attention output (pre-proj)
__device__ float g_H[ROWS * D_MODEL];         // xn + attn_proj
__device__ float g_HN[ROWS * D_MODEL];        // ln2(h)
__device__ float g_G[ROWS * 4 * D_MODEL];     // gelu(fc)

// ---------------- LayerNorm: one block per row, 256 threads ----------------
__global__ __launch_bounds__(256) void ln_kernel(const float* __restrict__ x,
                                                 const float* __restrict__ w,
                                                 const float* __restrict__ b,
                                                 float* __restrict__ y)
{
    int row = blockIdx.x;
    int t = threadIdx.x;
    const float4* xr = (const float4*)(x + (size_t)row * D_MODEL);
    float4 v = xr[t];
    float s  = v.x + v.y + v.z + v.w;
    float sq = v.x*v.x + v.y*v.y + v.z*v.z + v.w*v.w;
    #pragma unroll
    for (int o = 16; o > 0; o >>= 1) {
        s  += __shfl_xor_sync(0xFFFFFFFFu, s, o);
        sq += __shfl_xor_sync(0xFFFFFFFFu, sq, o);
    }
    __shared__ float ss[8], ssq[8];
    int wid = t >> 5, lane = t & 31;
    if (lane == 0) { ss[wid] = s; ssq[wid] = sq; }
    __syncthreads();
    if (wid == 0) {
        s  = (lane < 8) ? ss[lane]  : 0.0f;
        sq = (lane < 8) ? ssq[lane] : 0.0f;
        #pragma unroll
        for (int o = 4; o > 0; o >>= 1) {
            s  += __shfl_xor_sync(0xFFFFFFFFu, s, o);
            sq += __shfl_xor_sync(0xFFFFFFFFu, sq, o);
        }
        if (lane == 0) {
            float mu = s * (1.0f / D_MODEL);
            ss[0]  = mu;
            ssq[0] = rsqrtf(sq * (1.0f / D_MODEL) - mu * mu + 1e-5f);
        }
    }
    __syncthreads();
    float mu = ss[0], rstd = ssq[0];
    float4 wv = ((const float4*)w)[t];
    float4 bv = ((const float4*)b)[t];
    float4 r;
    r.x = (v.x - mu) * rstd * wv.x + bv.x;
    r.y = (v.y - mu) * rstd * wv.y + bv.y;
    r.z = (v.z - mu) * rstd * wv.z + bv.z;
    r.w = (v.w - mu) * rstd * wv.w + bv.w;
    ((float4*)(y + (size_t)row * D_MODEL))[t] = r;
}

// ---------------- SGEMM: C = epi(A[M,K] @ B[K,N] + bias, res) ----------------
// 128x128 tile, BK=8, 8x8 per thread, 256 threads.
#define EPI_BIAS      0
#define EPI_BIAS_GELU 1
#define EPI_BIAS_RES  2

template <int EPI>
__global__ __launch_bounds__(256) void sgemm_kernel(const float* __restrict__ A,
                                                    const float* __restrict__ B,
                                                    const float* __restrict__ bias,
                                                    const float* __restrict__ res,
                                                    float* __restrict__ C,
                                                    int M, int N, int K)
{
    __shared__ float As[8][128];
    __shared__ float Bs[8][128];
    int tid = threadIdx.x;
    int bx = blockIdx.x, by = blockIdx.y;
    int tx = tid & 15, ty = tid >> 4;

    float acc[8][8];
    #pragma unroll
    for (int i = 0; i < 8; i++)
        #pragma unroll
        for (int j = 0; j < 8; j++) acc[i][j] = 0.0f;

    int aRow = tid >> 1,  aCol = (tid & 1) * 4;   // A tile: 128 x 8
    int bRow = tid >> 5,  bCol = (tid & 31) * 4;  // B tile: 8 x 128

    const float* Ap = A + (size_t)(by * 128 + aRow) * K + aCol;
    const float* Bp = B + (size_t)bRow * N + bx * 128 + bCol;

    for (int k0 = 0; k0 < K; k0 += 8) {
        float4 a  = *(const float4*)(Ap + k0);
        float4 bv = *(const float4*)(Bp + (size_t)k0 * N);
        As[aCol + 0][aRow] = a.x;
        As[aCol + 1][aRow] = a.y;
        As[aCol + 2][aRow] = a.z;
        As[aCol + 3][aRow] = a.w;
        *(float4*)&Bs[bRow][bCol] = bv;
        __syncthreads();
        #pragma unroll
        for (int kk = 0; kk < 8; kk++) {
            float ar[8], br[8];
            #pragma unroll
            for (int i = 0; i < 8; i++) ar[i] = As[kk][ty * 8 + i];
            #pragma unroll
            for (int j = 0; j < 8; j++) br[j] = Bs[kk][tx * 8 + j];
            #pragma unroll
            for (int i = 0; i < 8; i++)
                #pragma unroll
                for (int j = 0; j < 8; j++)
                    acc[i][j] = fmaf(ar[i], br[j], acc[i][j]);
        }
        __syncthreads();
    }

    int row0 = by * 128 + ty * 8;
    int col0 = bx * 128 + tx * 8;
    #pragma unroll
    for (int i = 0; i < 8; i++) {
        size_t roff = (size_t)(row0 + i) * N;
        #pragma unroll
        for (int j = 0; j < 8; j++) {
            int col = col0 + j;
            float v = acc[i][j] + bias[col];
            if (EPI == EPI_BIAS_GELU)
                v = 0.5f * v * (1.0f + erff(v * 0.70710678118654752f));
            if (EPI == EPI_BIAS_RES)
                v += res[roff + col];
            C[roff + col] = v;
        }
    }
}

// ---------------- Flash attention (fp32, causal) ----------------
// grid: (SEQ/128, BATCH*NHEAD), block: 128 threads. 1 thread = 1 query row.
__global__ __launch_bounds__(128) void attn_kernel(const float* __restrict__ qkv,
                                                   float* __restrict__ out)
{
    __shared__ float Ks[32][64];
    __shared__ float Vs[32][64];
    int bh = blockIdx.y;
    int b = bh >> 4, h = bh & 15;
    int qi = blockIdx.x * 128 + threadIdx.x;

    const float* qp = qkv + ((size_t)(b * SEQ + qi) * 3 * D_MODEL) + h * HD;
    float q[64], o[64];
    #pragma unroll
    for (int d = 0; d < 64; d += 4) {
        float4 v = *(const float4*)(qp + d);
        q[d]   = v.x * 0.125f;  // 1/sqrt(64)
        q[d+1] = v.y * 0.125f;
        q[d+2] = v.z * 0.125f;
        q[d+3] = v.w * 0.125f;
    }
    #pragma unroll
    for (int d = 0; d < 64; d++) o[d] = 0.0f;
    float m = -3.0e38f, l = 0.0f;

    int kend = blockIdx.x * 128 + 128;   // exclusive upper bound of keys this block needs
    for (int kt = 0; kt < kend; kt += 32) {
        // cooperative load of K/V tiles (32 rows x 64)
        #pragma unroll
        for (int i = threadIdx.x; i < 32 * 16; i += 128) {
            int r = i >> 4, c = (i & 15) * 4;
            size_t base = ((size_t)(b * SEQ + kt + r) * 3 * D_MODEL) + h * HD + c;
            *(float4*)&Ks[r][c] = *(const float4*)(qkv + base + D_MODEL);
            *(float4*)&Vs[r][c] = *(const float4*)(qkv + base + 2 * D_MODEL);
        }
        __syncthreads();

        if (qi >= kt + 31) {
            // -------- full tile: all 32 keys valid, fully unrolled, s[] in regs
            float s[32];
            float tmax = -3.0e38f;
            #pragma unroll
            for (int j = 0; j < 32; j++) {
                float acc = 0.0f;
                #pragma unroll
                for (int d = 0; d < 64; d++) acc = fmaf(q[d], Ks[j][d], acc);
                s[j] = acc;
                tmax = fmaxf(tmax, acc);
            }
            float mn = fmaxf(m, tmax);
            float cc = __expf(m - mn);
            l *= cc;
            #pragma unroll
            for (int d = 0; d < 64; d++) o[d] *= cc;
            #pragma unroll
            for (int j = 0; j < 32; j++) {
                float p = __expf(s[j] - mn);
                l += p;
                #pragma unroll
                for (int d = 0; d < 64; d++) o[d] = fmaf(p, Vs[j][d], o[d]);
            }
            m = mn;
        } else if (qi >= kt) {
            // -------- partial (diagonal) tile: per-key online update
            int nv = qi - kt + 1;
            for (int j = 0; j < nv; j++) {
                float acc = 0.0f;
                #pragma unroll
                for (int d = 0; d < 64; d++) acc = fmaf(q[d], Ks[j][d], acc);
                float mn = fmaxf(m, acc);
                float cc = __expf(m - mn);
                float p  = __expf(acc - mn);
                l = l * cc + p;
                #pragma unroll
                for (int d = 0; d < 64; d++) o[d] = o[d] * cc + p * Vs[j][d];
                m = mn;
            }
        }
        __syncthreads();
    }

    float inv = 1.0f / l;
    float* op = out + ((size_t)(b * SEQ + qi) * D_MODEL) + h * HD;
    #pragma unroll
    for (int d = 0; d < 64; d += 4) {
        float4 v;
        v.x = o[d]   * inv;
        v.y = o[d+1] * inv;
        v.z = o[d+2] * inv;
        v.w = o[d+3] * inv;
        *(float4*)(op + d) = v;
    }
}

// ---------------- launch ----------------
extern "C" void kernel_launch(void* const* d_in, const int* in_sizes, int n_in,
                              void* d_out, int out_size)
{
    const float* x          = (const float*)d_in[0];
    const float* ln1_w      = (const float*)d_in[1];
    const float* ln1_b      = (const float*)d_in[2];
    const float* qkv_w      = (const float*)d_in[3];
    const float* qkv_b      = (const float*)d_in[4];
    const float* attn_out_w = (const float*)d_in[5];
    const float* attn_out_b = (const float*)d_in[6];
    const float* ln2_w      = (const float*)d_in[7];
    const float* ln2_b      = (const float*)d_in[8];
    const float* c_fc_w     = (const float*)d_in[9];
    const float* c_fc_b     = (const float*)d_in[10];
    const float* c_proj_w   = (const float*)d_in[11];
    const float* c_proj_b   = (const float*)d_in[12];
    float* out = (float*)d_out;

    float *XN, *QKV, *O, *H, *HN, *G;
    cudaGetSymbolAddress((void**)&XN,  g_XN);
    cudaGetSymbolAddress((void**)&QKV, g_QKV);
    cudaGetSymbolAddress((void**)&O,   g_O);
    cudaGetSymbolAddress((void**)&H,   g_H);
    cudaGetSymbolAddress((void**)&HN,  g_HN);
    cudaGetSymbolAddress((void**)&G,   g_G);

    // 1) xn = LN1(x)
    ln_kernel<<<ROWS, 256>>>(x, ln1_w, ln1_b, XN);

    // 2) qkv = xn @ qkv_w + qkv_b            [4096,1024]x[1024,3072]
    sgemm_kernel<EPI_BIAS><<<dim3(3 * D_MODEL / 128, ROWS / 128), 256>>>(
        XN, qkv_w, qkv_b, nullptr, QKV, ROWS, 3 * D_MODEL, D_MODEL);

    // 3) attention (causal, flash-style)
    attn_kernel<<<dim3(SEQ / 128, BATCH * NHEAD), 128>>>(QKV, O);

    // 4) h = xn + (o @ attn_out_w + attn_out_b)
    sgemm_kernel<EPI_BIAS_RES><<<dim3(D_MODEL / 128, ROWS / 128), 256>>>(
        O, attn_out_w, attn_out_b, XN, H, ROWS, D_MODEL, D_MODEL);

    // 5) hn = LN2(h)
    ln_kernel<<<ROWS, 256>>>(H, ln2_w, ln2_b, HN);

    // 6) g = gelu(hn @ c_fc_w + c_fc_b)      [4096,1024]x[1024,4096]
    sgemm_kernel<EPI_BIAS_GELU><<<dim3(4 * D_MODEL / 128, ROWS / 128), 256>>>(
        HN, c_fc_w, c_fc_b, nullptr, G, ROWS, 4 * D_MODEL, D_MODEL);

    // 7) out = hn + (g @ c_proj_w + c_proj_b) [4096,4096]x[4096,1024]
    sgemm_kernel<EPI_BIAS_RES><<<dim3(D_MODEL / 128, ROWS / 128), 256>>>(
        G, c_proj_w, c_proj_b, HN, out, ROWS, D_MODEL, 4 * D_MODEL);
}

// round 2
// speedup vs baseline: 1.1476x; 1.1476x over previous
#include <cuda_runtime.h>
#include <math.h>

#define D_MODEL 1024
#define SEQ 2048
#define BATCH 2
#define NHEAD 16
#define HD 64
#define ROWS (BATCH*SEQ)   // 4096

// ---------------- scratch (static device memory; no allocation) ----------------
__device__ float g_XN[ROWS * D_MODEL];        // ln1(x)
__device__ float g_QKV[ROWS * 3 * D_MODEL];   // qkv
__device__ float g_O[ROWS * D_MODEL];         // attention output (pre-proj)
__device__ float g_H[ROWS * D_MODEL];         // xn + attn_proj
__device__ float g_HN[ROWS * D_MODEL];        // ln2(h)
__device__ float g_G[ROWS * 4 * D_MODEL];     // gelu(fc)

// ---------------- LayerNorm: one block per row, 256 threads ----------------
__global__ __launch_bounds__(256) void ln_kernel(const float* __restrict__ x,
                                                 const float* __restrict__ w,
                                                 const float* __restrict__ b,
                                                 float* __restrict__ y)
{
    int row = blockIdx.x;
    int t = threadIdx.x;
    const float4* xr = (const float4*)(x + (size_t)row * D_MODEL);
    float4 v = xr[t];
    float s  = v.x + v.y + v.z + v.w;
    float sq = v.x*v.x + v.y*v.y + v.z*v.z + v.w*v.w;
    #pragma unroll
    for (int o = 16; o > 0; o >>= 1) {
        s  += __shfl_xor_sync(0xFFFFFFFFu, s, o);
        sq += __shfl_xor_sync(0xFFFFFFFFu, sq, o);
    }
    __shared__ float ss[8], ssq[8];
    int wid = t >> 5, lane = t & 31;
    if (lane == 0) { ss[wid] = s; ssq[wid] = sq; }
    __syncthreads();
    if (wid == 0) {
        s  = (lane < 8) ? ss[lane]  : 0.0f;
        sq = (lane < 8) ? ssq[lane] : 0.0f;
        #pragma unroll
        for (int o = 4; o > 0; o >>= 1) {
            s  += __shfl_xor_sync(0xFFFFFFFFu, s, o);
            sq += __shfl_xor_sync(0xFFFFFFFFu, sq, o);
        }
        if (lane == 0) {
            float mu = s * (1.0f / D_MODEL);
            ss[0]  = mu;
            ssq[0] = rsqrtf(sq * (1.0f / D_MODEL) - mu * mu + 1e-5f);
        }
    }
    __syncthreads();
    float mu = ss[0], rstd = ssq[0];
    float4 wv = ((const float4*)w)[t];
    float4 bv = ((const float4*)b)[t];
    float4 r;
    r.x = (v.x - mu) * rstd * wv.x + bv.x;
    r.y = (v.y - mu) * rstd * wv.y + bv.y;
    r.z = (v.z - mu) * rstd * wv.z + bv.z;
    r.w = (v.w - mu) * rstd * wv.w + bv.w;
    ((float4*)(y + (size_t)row * D_MODEL))[t] = r;
}

// ---------------- SGEMM: C = epi(A[M,K] @ B[K,N] + bias, res) ----------------
#define EPI_BIAS      0
#define EPI_BIAS_GELU 1
#define EPI_BIAS_RES  2

template <int EPI>
__global__ __launch_bounds__(256) void sgemm_kernel(const float* __restrict__ A,
                                                    const float* __restrict__ B,
                                                    const float* __restrict__ bias,
                                                    const float* __restrict__ res,
                                                    float* __restrict__ C,
                                                    int M, int N, int K)
{
    __shared__ float As[8][128];
    __shared__ float Bs[8][128];
    int tid = threadIdx.x;
    int bx = blockIdx.x, by = blockIdx.y;
    int tx = tid & 15, ty = tid >> 4;

    float acc[8][8];
    #pragma unroll
    for (int i = 0; i < 8; i++)
        #pragma unroll
        for (int j = 0; j < 8; j++) acc[i][j] = 0.0f;

    int aRow = tid >> 1,  aCol = (tid & 1) * 4;
    int bRow = tid >> 5,  bCol = (tid & 31) * 4;

    const float* Ap = A + (size_t)(by * 128 + aRow) * K + aCol;
    const float* Bp = B + (size_t)bRow * N + bx * 128 + bCol;

    for (int k0 = 0; k0 < K; k0 += 8) {
        float4 a  = *(const float4*)(Ap + k0);
        float4 bv = *(const float4*)(Bp + (size_t)k0 * N);
        As[aCol + 0][aRow] = a.x;
        As[aCol + 1][aRow] = a.y;
        As[aCol + 2][aRow] = a.z;
        As[aCol + 3][aRow] = a.w;
        *(float4*)&Bs[bRow][bCol] = bv;
        __syncthreads();
        #pragma unroll
        for (int kk = 0; kk < 8; kk++) {
            float ar[8], br[8];
            #pragma unroll
            for (int i = 0; i < 8; i++) ar[i] = As[kk][ty * 8 + i];
            #pragma unroll
            for (int j = 0; j < 8; j++) br[j] = Bs[kk][tx * 8 + j];
            #pragma unroll
            for (int i = 0; i < 8; i++)
                #pragma unroll
                for (int j = 0; j < 8; j++)
                    acc[i][j] = fmaf(ar[i], br[j], acc[i][j]);
        }
        __syncthreads();
    }

    int row0 = by * 128 + ty * 8;
    int col0 = bx * 128 + tx * 8;
    #pragma unroll
    for (int i = 0; i < 8; i++) {
        size_t roff = (size_t)(row0 + i) * N;
        #pragma unroll
        for (int j = 0; j < 8; j++) {
            int col = col0 + j;
            float v = acc[i][j] + bias[col];
            if (EPI == EPI_BIAS_GELU)
                v = 0.5f * v * (1.0f + erff(v * 0.70710678118654752f));
            if (EPI == EPI_BIAS_RES)
                v += res[roff + col];
            C[roff + col] = v;
        }
    }
}

// ---------------- Flash attention, GEMM-style tiles ----------------
// Block: 64 queries x (loop over 64-key tiles). 256 threads, 4x4 register
// tiles for both S=Q@K^T and O+=P@V. Q/K stored [dim][row] with XOR swizzle.
__global__ __launch_bounds__(256) void attn_kernel(const float* __restrict__ qkv,
                                                   float* __restrict__ out)
{
    __shared__ float Qs[64][64];   // [dim][qrow], swizzled
    __shared__ float Ks[64][64];   // [dim][key], swizzled; reused as Ps[key][qrow]
    __shared__ float Vs[64][64];   // [key][dim]

    int bh = blockIdx.y;
    int b = bh >> 4, h = bh & 15;
    int q0 = blockIdx.x * 64;
    int tid = threadIdx.x;
    int tx = tid & 15, ty = tid >> 4;

    // load Q tile transposed + swizzled, pre-scaled by 1/sqrt(hd)
    for (int i = tid; i < 64 * 16; i += 256) {
        int r = i >> 4, c = (i & 15) * 4;
        float4 v = *(const float4*)(qkv + ((size_t)(b * SEQ + q0 + r) * 3 * D_MODEL) + h * HD + c);
        Qs[c + 0][r ^ ((c + 0) & 28)] = v.x * 0.125f;
        Qs[c + 1][r ^ ((c + 1) & 28)] = v.y * 0.125f;
        Qs[c + 2][r ^ ((c + 2) & 28)] = v.z * 0.125f;
        Qs[c + 3][r ^ ((c + 3) & 28)] = v.w * 0.125f;
    }

    float o[4][4];
    float m[4], l[4];
    #pragma unroll
    for (int i = 0; i < 4; i++) {
        m[i] = -3.0e38f; l[i] = 0.0f;
        #pragma unroll
        for (int j = 0; j < 4; j++) o[i][j] = 0.0f;
    }
    __syncthreads();

    for (int kt = 0; kt <= q0; kt += 64) {
        // load K (transposed + swizzled) and V (natural layout)
        for (int i = tid; i < 64 * 16; i += 256) {
            int r = i >> 4, c = (i & 15) * 4;
            size_t base = ((size_t)(b * SEQ + kt + r) * 3 * D_MODEL) + h * HD + c;
            float4 kv = *(const float4*)(qkv + base + D_MODEL);
            Ks[c + 0][r ^ ((c + 0) & 28)] = kv.x;
            Ks[c + 1][r ^ ((c + 1) & 28)] = kv.y;
            Ks[c + 2][r ^ ((c + 2) & 28)] = kv.z;
            Ks[c + 3][r ^ ((c + 3) & 28)] = kv.w;
            *(float4*)&Vs[r][c] = *(const float4*)(qkv + base + 2 * D_MODEL);
        }
        __syncthreads();

        // S = Q @ K^T   (thread owns rows ty*4.., cols tx*4..)
        float s[4][4];
        #pragma unroll
        for (int i = 0; i < 4; i++)
            #pragma unroll
            for (int j = 0; j < 4; j++) s[i][j] = 0.0f;
        #pragma unroll 16
        for (int k = 0; k < 64; k++) {
            int swz = k & 28;
            float4 qv = *(const float4*)&Qs[k][(ty * 4) ^ swz];
            float4 kv = *(const float4*)&Ks[k][(tx * 4) ^ swz];
            float qr[4] = {qv.x, qv.y, qv.z, qv.w};
            float kc[4] = {kv.x, kv.y, kv.z, kv.w};
            #pragma unroll
            for (int i = 0; i < 4; i++)
                #pragma unroll
                for (int j = 0; j < 4; j++)
                    s[i][j] = fmaf(qr[i], kc[j], s[i][j]);
        }

        // causal mask (only the diagonal tile)
        if (kt == q0) {
            #pragma unroll
            for (int i = 0; i < 4; i++)
                #pragma unroll
                for (int j = 0; j < 4; j++)
                    if (tx * 4 + j > ty * 4 + i) s[i][j] = -3.0e38f;
        }

        // online softmax: per-row reductions across the 16-lane row group
        float p[4][4];
        #pragma unroll
        for (int i = 0; i < 4; i++) {
            float tmax = fmaxf(fmaxf(s[i][0], s[i][1]), fmaxf(s[i][2], s[i][3]));
            #pragma unroll
            for (int off = 8; off > 0; off >>= 1)
                tmax = fmaxf(tmax, __shfl_xor_sync(0xFFFFFFFFu, tmax, off, 16));
            float mn = fmaxf(m[i], tmax);
            float cc = __expf(m[i] - mn);
            m[i] = mn;
            float psum = 0.0f;
            #pragma unroll
            for (int j = 0; j < 4; j++) {
                p[i][j] = __expf(s[i][j] - mn);
                psum += p[i][j];
            }
            #pragma unroll
            for (int off = 8; off > 0; off >>= 1)
                psum += __shfl_xor_sync(0xFFFFFFFFu, psum, off, 16);
            l[i] = l[i] * cc + psum;
            #pragma unroll
            for (int j = 0; j < 4; j++) o[i][j] *= cc;
        }

        // P -> smem (reuse Ks buffer), stored [key][qrow] swizzled
        __syncthreads();
        #pragma unroll
        for (int j = 0; j < 4; j++) {
            int c = tx * 4 + j;
            int swz = c & 28;
            #pragma unroll
            for (int i = 0; i < 4; i++)
                Ks[c][(ty * 4 + i) ^ swz] = p[i][j];
        }
        __syncthreads();

        // O += P @ V
        #pragma unroll 16
        for (int k = 0; k < 64; k++) {
            int swz = k & 28;
            float4 pv = *(const float4*)&Ks[k][(ty * 4) ^ swz];
            float4 vv = *(const float4*)&Vs[k][tx * 4];
            float pr[4] = {pv.x, pv.y, pv.z, pv.w};
            float vd[4] = {vv.x, vv.y, vv.z, vv.w};
            #pragma unroll
            for (int i = 0; i < 4; i++)
                #pragma unroll
                for (int j = 0; j < 4; j++)
                    o[i][j] = fmaf(pr[i], vd[j], o[i][j]);
        }
        __syncthreads();
    }

    // epilogue: divide by l and store
    #pragma unroll
    for (int i = 0; i < 4; i++) {
        float inv = 1.0f / l[i];
        float4 r;
        r.x = o[i][0] * inv; r.y = o[i][1] * inv;
        r.z = o[i][2] * inv; r.w = o[i][3] * inv;
        *(float4*)(out + ((size_t)(b * SEQ + q0 + ty * 4 + i) * D_MODEL) + h * HD + tx * 4) = r;
    }
}

// ---------------- launch ----------------
extern "C" void kernel_launch(void* const* d_in, const int* in_sizes, int n_in,
                              void* d_out, int out_size)
{
    const float* x          = (const float*)d_in[0];
    const float* ln1_w      = (const float*)d_in[1];
    const float* ln1_b      = (const float*)d_in[2];
    const float* qkv_w      = (const float*)d_in[3];
    const float* qkv_b      = (const float*)d_in[4];
    const float* attn_out_w = (const float*)d_in[5];
    const float* attn_out_b = (const float*)d_in[6];
    const float* ln2_w      = (const float*)d_in[7];
    const float* ln2_b      = (const float*)d_in[8];
    const float* c_fc_w     = (const float*)d_in[9];
    const float* c_fc_b     = (const float*)d_in[10];
    const float* c_proj_w   = (const float*)d_in[11];
    const float* c_proj_b   = (const float*)d_in[12];
    float* out = (float*)d_out;

    float *XN, *QKV, *O, *H, *HN, *G;
    cudaGetSymbolAddress((void**)&XN,  g_XN);
    cudaGetSymbolAddress((void**)&QKV, g_QKV);
    cudaGetSymbolAddress((void**)&O,   g_O);
    cudaGetSymbolAddress((void**)&H,   g_H);
    cudaGetSymbolAddress((void**)&HN,  g_HN);
    cudaGetSymbolAddress((void**)&G,   g_G);

    // 1) xn = LN1(x)
    ln_kernel<<<ROWS, 256>>>(x, ln1_w, ln1_b, XN);

    // 2) qkv = xn @ qkv_w + qkv_b
    sgemm_kernel<EPI_BIAS><<<dim3(3 * D_MODEL / 128, ROWS / 128), 256>>>(
        XN, qkv_w, qkv_b, nullptr, QKV, ROWS, 3 * D_MODEL, D_MODEL);

    // 3) attention (causal, flash-style, GEMM tiles)
    attn_kernel<<<dim3(SEQ / 64, BATCH * NHEAD), 256>>>(QKV, O);

    // 4) h = xn + (o @ attn_out_w + attn_out_b)
    sgemm_kernel<EPI_BIAS_RES><<<dim3(D_MODEL / 128, ROWS / 128), 256>>>(
        O, attn_out_w, attn_out_b, XN, H, ROWS, D_MODEL, D_MODEL);

    // 5) hn = LN2(h)
    ln_kernel<<<ROWS, 256>>>(H, ln2_w, ln2_b, HN);

    // 6) g = gelu(hn @ c_fc_w + c_fc_b)
    sgemm_kernel<EPI_BIAS_GELU><<<dim3(4 * D_MODEL / 128, ROWS / 128), 256>>>(
        HN, c_fc_w, c_fc_b, nullptr, G, ROWS, 4 * D_MODEL, D_MODEL);

    // 7) out = hn + (g @ c_proj_w + c_proj_b)
    sgemm_kernel<EPI_BIAS_RES><<<dim3(D_MODEL / 128, ROWS / 128), 256>>>(
        G, c_proj_w, c_proj_b, HN, out, ROWS, D_MODEL, 4 * D_MODEL);
}

// round 3
// speedup vs baseline: 2.1893x; 1.9077x over previous
#include <cuda_runtime.h>
#include <math.h>
#include <stdint.h>

#define D_MODEL 1024
#define SEQ 2048
#define BATCH 2
#define NHEAD 16
#define HD 64
#define ROWS (BATCH*SEQ)   // 4096

// ---------------- scratch (static device memory; no allocation) ----------------
__device__ float g_XN[ROWS * D_MODEL];
__device__ float g_QKV[ROWS * 3 * D_MODEL];
__device__ float g_O[ROWS * D_MODEL];
__device__ float g_H[ROWS * D_MODEL];
__device__ float g_HN[ROWS * D_MODEL];
__device__ float g_G[ROWS * 4 * D_MODEL];

// ---------------- LayerNorm ----------------
__global__ __launch_bounds__(256) void ln_kernel(const float* __restrict__ x,
                                                 const float* __restrict__ w,
                                                 const float* __restrict__ b,
                                                 float* __restrict__ y)
{
    int row = blockIdx.x;
    int t = threadIdx.x;
    const float4* xr = (const float4*)(x + (size_t)row * D_MODEL);
    float4 v = xr[t];
    float s  = v.x + v.y + v.z + v.w;
    float sq = v.x*v.x + v.y*v.y + v.z*v.z + v.w*v.w;
    #pragma unroll
    for (int o = 16; o > 0; o >>= 1) {
        s  += __shfl_xor_sync(0xFFFFFFFFu, s, o);
        sq += __shfl_xor_sync(0xFFFFFFFFu, sq, o);
    }
    __shared__ float ss[8], ssq[8];
    int wid = t >> 5, lane = t & 31;
    if (lane == 0) { ss[wid] = s; ssq[wid] = sq; }
    __syncthreads();
    if (wid == 0) {
        s  = (lane < 8) ? ss[lane]  : 0.0f;
        sq = (lane < 8) ? ssq[lane] : 0.0f;
        #pragma unroll
        for (int o = 4; o > 0; o >>= 1) {
            s  += __shfl_xor_sync(0xFFFFFFFFu, s, o);
            sq += __shfl_xor_sync(0xFFFFFFFFu, sq, o);
        }
        if (lane == 0) {
            float mu = s * (1.0f / D_MODEL);
            ss[0]  = mu;
            ssq[0] = rsqrtf(sq * (1.0f / D_MODEL) - mu * mu + 1e-5f);
        }
    }
    __syncthreads();
    float mu = ss[0], rstd = ssq[0];
    float4 wv = ((const float4*)w)[t];
    float4 bv = ((const float4*)b)[t];
    float4 r;
    r.x = (v.x - mu) * rstd * wv.x + bv.x;
    r.y = (v.y - mu) * rstd * wv.y + bv.y;
    r.z = (v.z - mu) * rstd * wv.z + bv.z;
    r.w = (v.w - mu) * rstd * wv.w + bv.w;
    ((float4*)(y + (size_t)row * D_MODEL))[t] = r;
}

// ---------------- tf32 tensor-core GEMM ----------------
#define EPI_BIAS      0
#define EPI_BIAS_GELU 1
#define EPI_BIAS_RES  2

__device__ __forceinline__ uint32_t f2tf32(float x) {
    uint32_t r;
    asm("cvt.rna.tf32.f32 %0, %1;" : "=r"(r) : "f"(x));
    return r;
}

__device__ __forceinline__ void mma_tf32(float* d, const uint32_t* a, const uint32_t* b) {
    asm volatile(
        "mma.sync.aligned.m16n8k8.row.col.f32.tf32.tf32.f32 "
        "{%0,%1,%2,%3}, {%4,%5,%6,%7}, {%8,%9}, {%0,%1,%2,%3};\n"
        : "+f"(d[0]), "+f"(d[1]), "+f"(d[2]), "+f"(d[3])
        : "r"(a[0]), "r"(a[1]), "r"(a[2]), "r"(a[3]), "r"(b[0]), "r"(b[1]));
}

// C[M,N] = epi(A[M,K] @ B[K,N] + bias, res). Block tile 128x128, BK=32.
// 256 threads = 8 warps (2 m x 4 n), each warp 64x32 via 4x4 m16n8k8 tiles.
template <int EPI>
__global__ __launch_bounds__(256) void mma_gemm(const float* __restrict__ A,
                                                const float* __restrict__ B,
                                                const float* __restrict__ bias,
                                                const float* __restrict__ res,
                                                float* __restrict__ C,
                                                int M, int N, int K)
{
    __shared__ uint32_t As[128][36];   // [m][k], pad 36 -> A-frag LDS conflict-free
    __shared__ uint32_t Bs[32][136];   // [k][n], pad 136 -> B-frag LDS conflict-free

    int tid = threadIdx.x;
    int wid = tid >> 5, lane = tid & 31;
    int gid = lane >> 2, tig = lane & 3;
    int warp_m = wid & 1, warp_n = wid >> 1;
    int bx = blockIdx.x, by = blockIdx.y;

    float acc[4][4][4];
    #pragma unroll
    for (int mt = 0; mt < 4; mt++)
        #pragma unroll
        for (int nt = 0; nt < 4; nt++)
            #pragma unroll
            for (int r = 0; r < 4; r++) acc[mt][nt][r] = 0.0f;

    for (int k0 = 0; k0 < K; k0 += 32) {
        // A tile: 128m x 32k (1024 float4 loads, coalesced 128B per 8 lanes)
        #pragma unroll
        for (int i = tid; i < 128 * 8; i += 256) {
            int m = i >> 3, kq = (i & 7) * 4;
            float4 v = *(const float4*)(A + (size_t)(by * 128 + m) * K + k0 + kq);
            uint4 u = { f2tf32(v.x), f2tf32(v.y), f2tf32(v.z), f2tf32(v.w) };
            *(uint4*)&As[m][kq] = u;
        }
        // B tile: 32k x 128n (coalesced 512B per warp)
        #pragma unroll
        for (int i = tid; i < 32 * 32; i += 256) {
            int k = i >> 5, nq = (i & 31) * 4;
            float4 v = *(const float4*)(B + (size_t)(k0 + k) * N + bx * 128 + nq);
            uint4 u = { f2tf32(v.x), f2tf32(v.y), f2tf32(v.z), f2tf32(v.w) };
            *(uint4*)&Bs[k][nq] = u;
        }
        __syncthreads();

        #pragma unroll
        for (int ks = 0; ks < 4; ks++) {
            int kk = ks * 8;
            uint32_t af[4][4], bf[4][2];
            #pragma unroll
            for (int mt = 0; mt < 4; mt++) {
                int m0 = warp_m * 64 + mt * 16;
                af[mt][0] = As[m0 + gid    ][kk + tig    ];
                af[mt][1] = As[m0 + gid + 8][kk + tig    ];
                af[mt][2] = As[m0 + gid    ][kk + tig + 4];
                af[mt][3] = As[m0 + gid + 8][kk + tig + 4];
            }
            #pragma unroll
            for (int nt = 0; nt < 4; nt++) {
                int n0 = warp_n * 32 + nt * 8;
                bf[nt][0] = Bs[kk + tig    ][n0 + gid];
                bf[nt][1] = Bs[kk + tig + 4][n0 + gid];
            }
            #pragma unroll
            for (int mt = 0; mt < 4; mt++)
                #pragma unroll
                for (int nt = 0; nt < 4; nt++)
                    mma_tf32(acc[mt][nt], af[mt], bf[nt]);
        }
        __syncthreads();
    }

    // epilogue: each acc reg pair (c0,c1)/(c2,c3) is a float2 at (row, col..col+1)
    #pragma unroll
    for (int mt = 0; mt < 4; mt++) {
        #pragma unroll
        for (int nt = 0; nt < 4; nt++) {
            int row0 = by * 128 + warp_m * 64 + mt * 16 + gid;
            int col  = bx * 128 + warp_n * 32 + nt * 8 + tig * 2;
            float b0 = bias[col], b1 = bias[col + 1];
            #pragma unroll
            for (int half = 0; half < 2; half++) {
                int row = row0 + half * 8;
                float v0 = acc[mt][nt][half * 2 + 0] + b0;
                float v1 = acc[mt][nt][half * 2 + 1] + b1;
                if (EPI == EPI_BIAS_GELU) {
                    v0 = 0.5f * v0 * (1.0f + erff(v0 * 0.70710678118654752f));
                    v1 = 0.5f * v1 * (1.0f + erff(v1 * 0.70710678118654752f));
                }
                if (EPI == EPI_BIAS_RES) {
                    float2 rv = *(const float2*)(res + (size_t)row * N + col);
                    v0 += rv.x; v1 += rv.y;
                }
                float2 o2 = { v0, v1 };
                *(float2*)(C + (size_t)row * N + col) = o2;
            }
        }
    }
}

// ---------------- Flash attention, GEMM-style tiles (fp32) ----------------
__global__ __launch_bounds__(256) void attn_kernel(const float* __restrict__ qkv,
                                                   float* __restrict__ out)
{
    __shared__ float Qs[64][64];
    __shared__ float Ks[64][64];
    __shared__ float Vs[64][64];

    int bh = blockIdx.y;
    int b = bh >> 4, h = bh & 15;
    int q0 = blockIdx.x * 64;
    int tid = threadIdx.x;
    int tx = tid & 15, ty = tid >> 4;

    for (int i = tid; i < 64 * 16; i += 256) {
        int r = i >> 4, c = (i & 15) * 4;
        float4 v = *(const float4*)(qkv + ((size_t)(b * SEQ + q0 + r) * 3 * D_MODEL) + h * HD + c);
        Qs[c + 0][r ^ ((c + 0) & 28)] = v.x * 0.125f;
        Qs[c + 1][r ^ ((c + 1) & 28)] = v.y * 0.125f;
        Qs[c + 2][r ^ ((c + 2) & 28)] = v.z * 0.125f;
        Qs[c + 3][r ^ ((c + 3) & 28)] = v.w * 0.125f;
    }

    float o[4][4];
    float m[4], l[4];
    #pragma unroll
    for (int i = 0; i < 4; i++) {
        m[i] = -3.0e38f; l[i] = 0.0f;
        #pragma unroll
        for (int j = 0; j < 4; j++) o[i][j] = 0.0f;
    }
    __syncthreads();

    for (int kt = 0; kt <= q0; kt += 64) {
        for (int i = tid; i < 64 * 16; i += 256) {
            int r = i >> 4, c = (i & 15) * 4;
            size_t base = ((size_t)(b * SEQ + kt + r) * 3 * D_MODEL) + h * HD + c;
            float4 kv = *(const float4*)(qkv + base + D_MODEL);
            Ks[c + 0][r ^ ((c + 0) & 28)] = kv.x;
            Ks[c + 1][r ^ ((c + 1) & 28)] = kv.y;
            Ks[c + 2][r ^ ((c + 2) & 28)] = kv.z;
            Ks[c + 3][r ^ ((c + 3) & 28)] = kv.w;
            *(float4*)&Vs[r][c] = *(const float4*)(qkv + base + 2 * D_MODEL);
        }
        __syncthreads();

        float s[4][4];
        #pragma unroll
        for (int i = 0; i < 4; i++)
            #pragma unroll
            for (int j = 0; j < 4; j++) s[i][j] = 0.0f;
        #pragma unroll 16
        for (int k = 0; k < 64; k++) {
            int swz = k & 28;
            float4 qv = *(const float4*)&Qs[k][(ty * 4) ^ swz];
            float4 kv = *(const float4*)&Ks[k][(tx * 4) ^ swz];
            float qr[4] = {qv.x, qv.y, qv.z, qv.w};
            float kc[4] = {kv.x, kv.y, kv.z, kv.w};
            #pragma unroll
            for (int i = 0; i < 4; i++)
                #pragma unroll
                for (int j = 0; j < 4; j++)
                    s[i][j] = fmaf(qr[i], kc[j], s[i][j]);
        }

        if (kt == q0) {
            #pragma unroll
            for (int i = 0; i < 4; i++)
                #pragma unroll
                for (int j = 0; j < 4; j++)
                    if (tx * 4 + j > ty * 4 + i) s[i][j] = -3.0e38f;
        }

        float p[4][4];
        #pragma unroll
        for (int i = 0; i < 4; i++) {
            float tmax = fmaxf(fmaxf(s[i][0], s[i][1]), fmaxf(s[i][2], s[i][3]));
            #pragma unroll
            for (int off = 8; off > 0; off >>= 1)
                tmax = fmaxf(tmax, __shfl_xor_sync(0xFFFFFFFFu, tmax, off, 16));
            float mn = fmaxf(m[i], tmax);
            float cc = __expf(m[i] - mn);
            m[i] = mn;
            float psum = 0.0f;
            #pragma unroll
            for (int j = 0; j < 4; j++) {
                p[i][j] = __expf(s[i][j] - mn);
                psum += p[i][j];
            }
            #pragma unroll
            for (int off = 8; off > 0; off >>= 1)
                psum += __shfl_xor_sync(0xFFFFFFFFu, psum, off, 16);
            l[i] = l[i] * cc + psum;
            #pragma unroll
            for (int j = 0; j < 4; j++) o[i][j] *= cc;
        }

        __syncthreads();
        #pragma unroll
        for (int j = 0; j < 4; j++) {
            int c = tx * 4 + j;
            int swz = c & 28;
            #pragma unroll
            for (int i = 0; i < 4; i++)
                Ks[c][(ty * 4 + i) ^ swz] = p[i][j];
        }
        __syncthreads();

        #pragma unroll 16
        for (int k = 0; k < 64; k++) {
            int swz = k & 28;
            float4 pv = *(const float4*)&Ks[k][(ty * 4) ^ swz];
            float4 vv = *(const float4*)&Vs[k][tx * 4];
            float pr[4] = {pv.x, pv.y, pv.z, pv.w};
            float vd[4] = {vv.x, vv.y, vv.z, vv.w};
            #pragma unroll
            for (int i = 0; i < 4; i++)
                #pragma unroll
                for (int j = 0; j < 4; j++)
                    o[i][j] = fmaf(pr[i], vd[j], o[i][j]);
        }
        __syncthreads();
    }

    #pragma unroll
    for (int i = 0; i < 4; i++) {
        float inv = 1.0f / l[i];
        float4 r;
        r.x = o[i][0] * inv; r.y = o[i][1] * inv;
        r.z = o[i][2] * inv; r.w = o[i][3] * inv;
        *(float4*)(out + ((size_t)(b * SEQ + q0 + ty * 4 + i) * D_MODEL) + h * HD + tx * 4) = r;
    }
}

// ---------------- launch ----------------
extern "C" void kernel_launch(void* const* d_in, const int* in_sizes, int n_in,
                              void* d_out, int out_size)
{
    const float* x          = (const float*)d_in[0];
    const float* ln1_w      = (const float*)d_in[1];
    const float* ln1_b      = (const float*)d_in[2];
    const float* qkv_w      = (const float*)d_in[3];
    const float* qkv_b      = (const float*)d_in[4];
    const float* attn_out_w = (const float*)d_in[5];
    const float* attn_out_b = (const float*)d_in[6];
    const float* ln2_w      = (const float*)d_in[7];
    const float* ln2_b      = (const float*)d_in[8];
    const float* c_fc_w     = (const float*)d_in[9];
    const float* c_fc_b     = (const float*)d_in[10];
    const float* c_proj_w   = (const float*)d_in[11];
    const float* c_proj_b   = (const float*)d_in[12];
    float* out = (float*)d_out;

    float *XN, *QKV, *O, *H, *HN, *G;
    cudaGetSymbolAddress((void**)&XN,  g_XN);
    cudaGetSymbolAddress((void**)&QKV, g_QKV);
    cudaGetSymbolAddress((void**)&O,   g_O);
    cudaGetSymbolAddress((void**)&H,   g_H);
    cudaGetSymbolAddress((void**)&HN,  g_HN);
    cudaGetSymbolAddress((void**)&G,   g_G);

    ln_kernel<<<ROWS, 256>>>(x, ln1_w, ln1_b, XN);

    mma_gemm<EPI_BIAS><<<dim3(3 * D_MODEL / 128, ROWS / 128), 256>>>(
        XN, qkv_w, qkv_b, nullptr, QKV, ROWS, 3 * D_MODEL, D_MODEL);

    attn_kernel<<<dim3(SEQ / 64, BATCH * NHEAD), 256>>>(QKV, O);

    mma_gemm<EPI_BIAS_RES><<<dim3(D_MODEL / 128, ROWS / 128), 256>>>(
        O, attn_out_w, attn_out_b, XN, H, ROWS, D_MODEL, D_MODEL);

    ln_kernel<<<ROWS, 256>>>(H, ln2_w, ln2_b, HN);

    mma_gemm<EPI_BIAS_GELU><<<dim3(4 * D_MODEL / 128, ROWS / 128), 256>>>(
        HN, c_fc_w, c_fc_b, nullptr, G, ROWS, 4 * D_MODEL, D_MODEL);

    mma_gemm<EPI_BIAS_RES><<<dim3(D_MODEL / 128, ROWS / 128), 256>>>(
        G, c_proj_w, c_proj_b, HN, out, ROWS, D_MODEL, 4 * D_MODEL);
}

// round 4
// speedup vs baseline: 2.2724x; 1.0379x over previous
#include <cuda_runtime.h>
#include <math.h>
#include <stdint.h>

#define D_MODEL 1024
#define SEQ 2048
#define BATCH 2
#define NHEAD 16
#define HD 64
#define ROWS (BATCH*SEQ)   // 4096

// ---------------- scratch (static device memory; no allocation) ----------------
__device__ float g_XN[ROWS * D_MODEL];
__device__ float g_QKV[ROWS * 3 * D_MODEL];
__device__ float g_O[ROWS * D_MODEL];
__device__ float g_H[ROWS * D_MODEL];
__device__ float g_HN[ROWS * D_MODEL];
__device__ float g_G[ROWS * 4 * D_MODEL];

// ---------------- LayerNorm ----------------
__global__ __launch_bounds__(256) void ln_kernel(const float* __restrict__ x,
                                                 const float* __restrict__ w,
                                                 const float* __restrict__ b,
                                                 float* __restrict__ y)
{
    int row = blockIdx.x;
    int t = threadIdx.x;
    const float4* xr = (const float4*)(x + (size_t)row * D_MODEL);
    float4 v = xr[t];
    float s  = v.x + v.y + v.z + v.w;
    float sq = v.x*v.x + v.y*v.y + v.z*v.z + v.w*v.w;
    #pragma unroll
    for (int o = 16; o > 0; o >>= 1) {
        s  += __shfl_xor_sync(0xFFFFFFFFu, s, o);
        sq += __shfl_xor_sync(0xFFFFFFFFu, sq, o);
    }
    __shared__ float ss[8], ssq[8];
    int wid = t >> 5, lane = t & 31;
    if (lane == 0) { ss[wid] = s; ssq[wid] = sq; }
    __syncthreads();
    if (wid == 0) {
        s  = (lane < 8) ? ss[lane]  : 0.0f;
        sq = (lane < 8) ? ssq[lane] : 0.0f;
        #pragma unroll
        for (int o = 4; o > 0; o >>= 1) {
            s  += __shfl_xor_sync(0xFFFFFFFFu, s, o);
            sq += __shfl_xor_sync(0xFFFFFFFFu, sq, o);
        }
        if (lane == 0) {
            float mu = s * (1.0f / D_MODEL);
            ss[0]  = mu;
            ssq[0] = rsqrtf(sq * (1.0f / D_MODEL) - mu * mu + 1e-5f);
        }
    }
    __syncthreads();
    float mu = ss[0], rstd = ssq[0];
    float4 wv = ((const float4*)w)[t];
    float4 bv = ((const float4*)b)[t];
    float4 r;
    r.x = (v.x - mu) * rstd * wv.x + bv.x;
    r.y = (v.y - mu) * rstd * wv.y + bv.y;
    r.z = (v.z - mu) * rstd * wv.z + bv.z;
    r.w = (v.w - mu) * rstd * wv.w + bv.w;
    ((float4*)(y + (size_t)row * D_MODEL))[t] = r;
}

// ---------------- tf32 tensor-core GEMM (pipelined) ----------------
#define EPI_BIAS      0
#define EPI_BIAS_GELU 1
#define EPI_BIAS_RES  2

__device__ __forceinline__ uint32_t f2tf32(float x) {
    uint32_t r;
    asm("cvt.rna.tf32.f32 %0, %1;" : "=r"(r) : "f"(x));
    return r;
}

__device__ __forceinline__ void mma_tf32(float* d, const uint32_t* a, const uint32_t* b) {
    asm volatile(
        "mma.sync.aligned.m16n8k8.row.col.f32.tf32.tf32.f32 "
        "{%0,%1,%2,%3}, {%4,%5,%6,%7}, {%8,%9}, {%0,%1,%2,%3};\n"
        : "+f"(d[0]), "+f"(d[1]), "+f"(d[2]), "+f"(d[3])
        : "r"(a[0]), "r"(a[1]), "r"(a[2]), "r"(a[3]), "r"(b[0]), "r"(b[1]));
}

// C[M,N] = epi(A[M,K] @ B[K,N] + bias, res). Block tile 128x128, BK=32.
// 256 threads = 8 warps (2m x 4n), warp tile 64x32 via 4x4 m16n8k8.
// Double-buffered smem + register prefetch: LDG(i+1) issued before compute(i).
template <int EPI>
__global__ __launch_bounds__(256) void mma_gemm(const float* __restrict__ A,
                                                const float* __restrict__ B,
                                                const float* __restrict__ bias,
                                                const float* __restrict__ res,
                                                float* __restrict__ C,
                                                int M, int N, int K)
{
    __shared__ uint32_t As[2][128][36];
    __shared__ uint32_t Bs[2][32][136];

    int tid = threadIdx.x;
    int wid = tid >> 5, lane = tid & 31;
    int gid = lane >> 2, tig = lane & 3;
    int warp_m = wid & 1, warp_n = wid >> 1;
    int bx = blockIdx.x, by = blockIdx.y;

    // per-thread LDG coordinates (4 float4 each for A and B)
    const float* Ap[4];
    const float* Bp[4];
    int aM[4], aK[4], bK[4], bN[4];
    #pragma unroll
    for (int j = 0; j < 4; j++) {
        int ia = tid + j * 256;
        aM[j] = ia >> 3; aK[j] = (ia & 7) * 4;
        Ap[j] = A + (size_t)(by * 128 + aM[j]) * K + aK[j];
        int ib = tid + j * 256;
        bK[j] = ib >> 5; bN[j] = (ib & 31) * 4;
        Bp[j] = B + (size_t)bK[j] * N + bx * 128 + bN[j];
    }

    float acc[4][4][4];
    #pragma unroll
    for (int mt = 0; mt < 4; mt++)
        #pragma unroll
        for (int nt = 0; nt < 4; nt++)
            #pragma unroll
            for (int r = 0; r < 4; r++) acc[mt][nt][r] = 0.0f;

    float4 ra[4], rb[4];

    // prologue: load tile 0 -> regs -> smem[0]
    #pragma unroll
    for (int j = 0; j < 4; j++) {
        ra[j] = *(const float4*)(Ap[j]);
        rb[j] = *(const float4*)(Bp[j]);
    }
    #pragma unroll
    for (int j = 0; j < 4; j++) {
        uint4 ua = { f2tf32(ra[j].x), f2tf32(ra[j].y), f2tf32(ra[j].z), f2tf32(ra[j].w) };
        *(uint4*)&As[0][aM[j]][aK[j]] = ua;
        uint4 ub = { f2tf32(rb[j].x), f2tf32(rb[j].y), f2tf32(rb[j].z), f2tf32(rb[j].w) };
        *(uint4*)&Bs[0][bK[j]][bN[j]] = ub;
    }
    __syncthreads();

    int buf = 0;
    for (int k0 = 32; k0 <= K; k0 += 32) {
        // prefetch next tile into registers (overlaps with compute below)
        if (k0 < K) {
            #pragma unroll
            for (int j = 0; j < 4; j++) {
                ra[j] = *(const float4*)(Ap[j] + k0);
                rb[j] = *(const float4*)(Bp[j] + (size_t)k0 * N);
            }
        }

        // compute on current buffer
        #pragma unroll
        for (int ks = 0; ks < 4; ks++) {
            int kk = ks * 8;
            uint32_t af[4][4], bf[4][2];
            #pragma unroll
            for (int mt = 0; mt < 4; mt++) {
                int m0 = warp_m * 64 + mt * 16;
                af[mt][0] = As[buf][m0 + gid    ][kk + tig    ];
                af[mt][1] = As[buf][m0 + gid + 8][kk + tig    ];
                af[mt][2] = As[buf][m0 + gid    ][kk + tig + 4];
                af[mt][3] = As[buf][m0 + gid + 8][kk + tig + 4];
            }
            #pragma unroll
            for (int nt = 0; nt < 4; nt++) {
                int n0 = warp_n * 32 + nt * 8;
                bf[nt][0] = Bs[buf][kk + tig    ][n0 + gid];
                bf[nt][1] = Bs[buf][kk + tig + 4][n0 + gid];
            }
            #pragma unroll
            for (int mt = 0; mt < 4; mt++)
                #pragma unroll
                for (int nt = 0; nt < 4; nt++)
                    mma_tf32(acc[mt][nt], af[mt], bf[nt]);
        }

        // store prefetched tile into the other buffer
        if (k0 < K) {
            int nb = buf ^ 1;
            #pragma unroll
            for (int j = 0; j < 4; j++) {
                uint4 ua = { f2tf32(ra[j].x), f2tf32(ra[j].y), f2tf32(ra[j].z), f2tf32(ra[j].w) };
                *(uint4*)&As[nb][aM[j]][aK[j]] = ua;
                uint4 ub = { f2tf32(rb[j].x), f2tf32(rb[j].y), f2tf32(rb[j].z), f2tf32(rb[j].w) };
                *(uint4*)&Bs[nb][bK[j]][bN[j]] = ub;
            }
            __syncthreads();
            buf = nb;
        }
    }

    // epilogue
    #pragma unroll
    for (int mt = 0; mt < 4; mt++) {
        #pragma unroll
        for (int nt = 0; nt < 4; nt++) {
            int row0 = by * 128 + warp_m * 64 + mt * 16 + gid;
            int col  = bx * 128 + warp_n * 32 + nt * 8 + tig * 2;
            float b0 = bias[col], b1 = bias[col + 1];
            #pragma unroll
            for (int half = 0; half < 2; half++) {
                int row = row0 + half * 8;
                float v0 = acc[mt][nt][half * 2 + 0] + b0;
                float v1 = acc[mt][nt][half * 2 + 1] + b1;
                if (EPI == EPI_BIAS_GELU) {
                    v0 = 0.5f * v0 * (1.0f + erff(v0 * 0.70710678118654752f));
                    v1 = 0.5f * v1 * (1.0f + erff(v1 * 0.70710678118654752f));
                }
                if (EPI == EPI_BIAS_RES) {
                    float2 rv = *(const float2*)(res + (size_t)row * N + col);
                    v0 += rv.x; v1 += rv.y;
                }
                float2 o2 = { v0, v1 };
                *(float2*)(C + (size_t)row * N + col) = o2;
            }
        }
    }
}

// ---------------- Flash attention, GEMM-style tiles (fp32) ----------------
__global__ __launch_bounds__(256) void attn_kernel(const float* __restrict__ qkv,
                                                   float* __restrict__ out)
{
    __shared__ float Qs[64][64];
    __shared__ float Ks[64][64];
    __shared__ float Vs[64][64];

    int bh = blockIdx.y;
    int b = bh >> 4, h = bh & 15;
    int q0 = blockIdx.x * 64;
    int tid = threadIdx.x;
    int tx = tid & 15, ty = tid >> 4;

    for (int i = tid; i < 64 * 16; i += 256) {
        int r = i >> 4, c = (i & 15) * 4;
        float4 v = *(const float4*)(qkv + ((size_t)(b * SEQ + q0 + r) * 3 * D_MODEL) + h * HD + c);
        Qs[c + 0][r ^ ((c + 0) & 28)] = v.x * 0.125f;
        Qs[c + 1][r ^ ((c + 1) & 28)] = v.y * 0.125f;
        Qs[c + 2][r ^ ((c + 2) & 28)] = v.z * 0.125f;
        Qs[c + 3][r ^ ((c + 3) & 28)] = v.w * 0.125f;
    }

    float o[4][4];
    float m[4], l[4];
    #pragma unroll
    for (int i = 0; i < 4; i++) {
        m[i] = -3.0e38f; l[i] = 0.0f;
        #pragma unroll
        for (int j = 0; j < 4; j++) o[i][j] = 0.0f;
    }
    __syncthreads();

    for (int kt = 0; kt <= q0; kt += 64) {
        for (int i = tid; i < 64 * 16; i += 256) {
            int r = i >> 4, c = (i & 15) * 4;
            size_t base = ((size_t)(b * SEQ + kt + r) * 3 * D_MODEL) + h * HD + c;
            float4 kv = *(const float4*)(qkv + base + D_MODEL);
            Ks[c + 0][r ^ ((c + 0) & 28)] = kv.x;
            Ks[c + 1][r ^ ((c + 1) & 28)] = kv.y;
            Ks[c + 2][r ^ ((c + 2) & 28)] = kv.z;
            Ks[c + 3][r ^ ((c + 3) & 28)] = kv.w;
            *(float4*)&Vs[r][c] = *(const float4*)(qkv + base + 2 * D_MODEL);
        }
        __syncthreads();

        float s[4][4];
        #pragma unroll
        for (int i = 0; i < 4; i++)
            #pragma unroll
            for (int j = 0; j < 4; j++) s[i][j] = 0.0f;
        #pragma unroll 16
        for (int k = 0; k < 64; k++) {
            int swz = k & 28;
            float4 qv = *(const float4*)&Qs[k][(ty * 4) ^ swz];
            float4 kv = *(const float4*)&Ks[k][(tx * 4) ^ swz];
            float qr[4] = {qv.x, qv.y, qv.z, qv.w};
            float kc[4] = {kv.x, kv.y, kv.z, kv.w};
            #pragma unroll
            for (int i = 0; i < 4; i++)
                #pragma unroll
                for (int j = 0; j < 4; j++)
                    s[i][j] = fmaf(qr[i], kc[j], s[i][j]);
        }

        if (kt == q0) {
            #pragma unroll
            for (int i = 0; i < 4; i++)
                #pragma unroll
                for (int j = 0; j < 4; j++)
                    if (tx * 4 + j > ty * 4 + i) s[i][j] = -3.0e38f;
        }

        float p[4][4];
        #pragma unroll
        for (int i = 0; i < 4; i++) {
            float tmax = fmaxf(fmaxf(s[i][0], s[i][1]), fmaxf(s[i][2], s[i][3]));
            #pragma unroll
            for (int off = 8; off > 0; off >>= 1)
                tmax = fmaxf(tmax, __shfl_xor_sync(0xFFFFFFFFu, tmax, off, 16));
            float mn = fmaxf(m[i], tmax);
            float cc = __expf(m[i] - mn);
            m[i] = mn;
            float psum = 0.0f;
            #pragma unroll
            for (int j = 0; j < 4; j++) {
                p[i][j] = __expf(s[i][j] - mn);
                psum += p[i][j];
            }
            #pragma unroll
            for (int off = 8; off > 0; off >>= 1)
                psum += __shfl_xor_sync(0xFFFFFFFFu, psum, off, 16);
            l[i] = l[i] * cc + psum;
            #pragma unroll
            for (int j = 0; j < 4; j++) o[i][j] *= cc;
        }

        __syncthreads();
        #pragma unroll
        for (int j = 0; j < 4; j++) {
            int c = tx * 4 + j;
            int swz = c & 28;
            #pragma unroll
            for (int i = 0; i < 4; i++)
                Ks[c][(ty * 4 + i) ^ swz] = p[i][j];
        }
        __syncthreads();

        #pragma unroll 16
        for (int k = 0; k < 64; k++) {
            int swz = k & 28;
            float4 pv = *(const float4*)&Ks[k][(ty * 4) ^ swz];
            float4 vv = *(const float4*)&Vs[k][tx * 4];
            float pr[4] = {pv.x, pv.y, pv.z, pv.w};
            float vd[4] = {vv.x, vv.y, vv.z, vv.w};
            #pragma unroll
            for (int i = 0; i < 4; i++)
                #pragma unroll
                for (int j = 0; j < 4; j++)
                    o[i][j] = fmaf(pr[i], vd[j], o[i][j]);
        }
        __syncthreads();
    }

    #pragma unroll
    for (int i = 0; i < 4; i++) {
        float inv = 1.0f / l[i];
        float4 r;
        r.x = o[i][0] * inv; r.y = o[i][1] * inv;
        r.z = o[i][2] * inv; r.w = o[i][3] * inv;
        *(float4*)(out + ((size_t)(b * SEQ + q0 + ty * 4 + i) * D_MODEL) + h * HD + tx * 4) = r;
    }
}

// ---------------- launch ----------------
extern "C" void kernel_launch(void* const* d_in, const int* in_sizes, int n_in,
                              void* d_out, int out_size)
{
    const float* x          = (const float*)d_in[0];
    const float* ln1_w      = (const float*)d_in[1];
    const float* ln1_b      = (const float*)d_in[2];
    const float* qkv_w      = (const float*)d_in[3];
    const float* qkv_b      = (const float*)d_in[4];
    const float* attn_out_w = (const float*)d_in[5];
    const float* attn_out_b = (const float*)d_in[6];
    const float* ln2_w      = (const float*)d_in[7];
    const float* ln2_b      = (const float*)d_in[8];
    const float* c_fc_w     = (const float*)d_in[9];
    const float* c_fc_b     = (const float*)d_in[10];
    const float* c_proj_w   = (const float*)d_in[11];
    const float* c_proj_b   = (const float*)d_in[12];
    float* out = (float*)d_out;

    float *XN, *QKV, *O, *H, *HN, *G;
    cudaGetSymbolAddress((void**)&XN,  g_XN);
    cudaGetSymbolAddress((void**)&QKV, g_QKV);
    cudaGetSymbolAddress((void**)&O,   g_O);
    cudaGetSymbolAddress((void**)&H,   g_H);
    cudaGetSymbolAddress((void**)&HN,  g_HN);
    cudaGetSymbolAddress((void**)&G,   g_G);

    ln_kernel<<<ROWS, 256>>>(x, ln1_w, ln1_b, XN);

    mma_gemm<EPI_BIAS><<<dim3(3 * D_MODEL / 128, ROWS / 128), 256>>>(
        XN, qkv_w, qkv_b, nullptr, QKV, ROWS, 3 * D_MODEL, D_MODEL);

    attn_kernel<<<dim3(SEQ / 64, BATCH * NHEAD), 256>>>(QKV, O);

    mma_gemm<EPI_BIAS_RES><<<dim3(D_MODEL / 128, ROWS / 128), 256>>>(
        O, attn_out_w, attn_out_b, XN, H, ROWS, D_MODEL, D_MODEL);

    ln_kernel<<<ROWS, 256>>>(H, ln2_w, ln2_b, HN);

    mma_gemm<EPI_BIAS_GELU><<<dim3(4 * D_MODEL / 128, ROWS / 128), 256>>>(
        HN, c_fc_w, c_fc_b, nullptr, G, ROWS, 4 * D_MODEL, D_MODEL);

    mma_gemm<EPI_BIAS_RES><<<dim3(D_MODEL / 128, ROWS / 128), 256>>>(
        G, c_proj_w, c_proj_b, HN, out, ROWS, D_MODEL, 4 * D_MODEL);
}

// round 5
// speedup vs baseline: 2.8082x; 1.2358x over previous
#include <cuda_runtime.h>
#include <math.h>
#include <stdint.h>

#define D_MODEL 1024
#define SEQ 2048
#define BATCH 2
#define NHEAD 16
#define HD 64
#define ROWS (BATCH*SEQ)   // 4096

// ---------------- scratch (static device memory; no allocation) ----------------
__device__ float    g_XN [ROWS * D_MODEL];       // ln1(x) fp32 (residual)
__device__ uint32_t g_XNt[ROWS * D_MODEL];       // ln1(x) tf32
__device__ float    g_QKV[ROWS * 3 * D_MODEL];   // qkv fp32 (attention input)
__device__ uint32_t g_Ot [ROWS * D_MODEL];       // attention out, tf32
__device__ float    g_H  [ROWS * D_MODEL];       // xn + attn_proj fp32
__device__ float    g_HN [ROWS * D_MODEL];       // ln2(h) fp32 (residual)
__device__ uint32_t g_HNt[ROWS * D_MODEL];       // ln2(h) tf32
__device__ uint32_t g_Gt [ROWS * 4 * D_MODEL];   // gelu(fc) tf32
// tf32 weight copies
__device__ uint32_t g_Wqkv [D_MODEL * 3 * D_MODEL];
__device__ uint32_t g_Wproj[D_MODEL * D_MODEL];
__device__ uint32_t g_Wfc  [D_MODEL * 4 * D_MODEL];
__device__ uint32_t g_Wpr2 [4 * D_MODEL * D_MODEL];

__device__ __forceinline__ uint32_t f2tf32(float x) {
    uint32_t r;
    asm("cvt.rna.tf32.f32 %0, %1;" : "=r"(r) : "f"(x));
    return r;
}

// ---------------- weight -> tf32 conversion ----------------
__global__ __launch_bounds__(256) void cvt_tf32_kernel(const float* __restrict__ in,
                                                       uint32_t* __restrict__ out)
{
    int i = (blockIdx.x * 256 + threadIdx.x) * 4;
    float4 v = *(const float4*)(in + i);
    uint4 u = { f2tf32(v.x), f2tf32(v.y), f2tf32(v.z), f2tf32(v.w) };
    *(uint4*)(out + i) = u;
}

// ---------------- LayerNorm (writes fp32 + tf32 copies) ----------------
__global__ __launch_bounds__(256) void ln_kernel(const float* __restrict__ x,
                                                 const float* __restrict__ w,
                                                 const float* __restrict__ b,
                                                 float* __restrict__ y,
                                                 uint32_t* __restrict__ ytf)
{
    int row = blockIdx.x;
    int t = threadIdx.x;
    const float4* xr = (const float4*)(x + (size_t)row * D_MODEL);
    float4 v = xr[t];
    float s  = v.x + v.y + v.z + v.w;
    float sq = v.x*v.x + v.y*v.y + v.z*v.z + v.w*v.w;
    #pragma unroll
    for (int o = 16; o > 0; o >>= 1) {
        s  += __shfl_xor_sync(0xFFFFFFFFu, s, o);
        sq += __shfl_xor_sync(0xFFFFFFFFu, sq, o);
    }
    __shared__ float ss[8], ssq[8];
    int wid = t >> 5, lane = t & 31;
    if (lane == 0) { ss[wid] = s; ssq[wid] = sq; }
    __syncthreads();
    if (wid == 0) {
        s  = (lane < 8) ? ss[lane]  : 0.0f;
        sq = (lane < 8) ? ssq[lane] : 0.0f;
        #pragma unroll
        for (int o = 4; o > 0; o >>= 1) {
            s  += __shfl_xor_sync(0xFFFFFFFFu, s, o);
            sq += __shfl_xor_sync(0xFFFFFFFFu, sq, o);
        }
        if (lane == 0) {
            float mu = s * (1.0f / D_MODEL);
            ss[0]  = mu;
            ssq[0] = rsqrtf(sq * (1.0f / D_MODEL) - mu * mu + 1e-5f);
        }
    }
    __syncthreads();
    float mu = ss[0], rstd = ssq[0];
    float4 wv = ((const float4*)w)[t];
    float4 bv = ((const float4*)b)[t];
    float4 r;
    r.x = (v.x - mu) * rstd * wv.x + bv.x;
    r.y = (v.y - mu) * rstd * wv.y + bv.y;
    r.z = (v.z - mu) * rstd * wv.z + bv.z;
    r.w = (v.w - mu) * rstd * wv.w + bv.w;
    ((float4*)(y + (size_t)row * D_MODEL))[t] = r;
    uint4 u = { f2tf32(r.x), f2tf32(r.y), f2tf32(r.z), f2tf32(r.w) };
    ((uint4*)(ytf + (size_t)row * D_MODEL))[t] = u;
}

// ---------------- tf32 tensor-core GEMM (cp.async 2-stage) ----------------
#define EPI_BIAS      0
#define EPI_BIAS_GELU 1
#define EPI_BIAS_RES  2

__device__ __forceinline__ void mma_tf32(float* d, const uint32_t* a, const uint32_t* b) {
    asm volatile(
        "mma.sync.aligned.m16n8k8.row.col.f32.tf32.tf32.f32 "
        "{%0,%1,%2,%3}, {%4,%5,%6,%7}, {%8,%9}, {%0,%1,%2,%3};\n"
        : "+f"(d[0]), "+f"(d[1]), "+f"(d[2]), "+f"(d[3])
        : "r"(a[0]), "r"(a[1]), "r"(a[2]), "r"(a[3]), "r"(b[0]), "r"(b[1]));
}

__device__ __forceinline__ void cp16(uint32_t dst, const void* src) {
    asm volatile("cp.async.cg.shared.global [%0], [%1], 16;\n" :: "r"(dst), "l"(src));
}
__device__ __forceinline__ void cp_commit() {
    asm volatile("cp.async.commit_group;\n");
}
template <int N>
__device__ __forceinline__ void cp_wait() {
    asm volatile("cp.async.wait_group %0;\n" :: "n"(N));
}

#define AS_STRIDE 36
#define BS_STRIDE 136
#define A_STAGE (128 * AS_STRIDE)   // uint32 count
#define B_STAGE (32 * BS_STRIDE)
#define GEMM_SMEM_BYTES ((2 * A_STAGE + 2 * B_STAGE) * 4)

// C[M,N] = epi(A[M,K] @ B[K,N] + bias, res). A,B pre-rounded tf32 (uint32).
// Block tile 128x128, BK=32, 256 threads = 8 warps (2m x 4n), warp 64x32.
template <int EPI>
__global__ __launch_bounds__(256, 2) void mma_gemm(const uint32_t* __restrict__ A,
                                                   const uint32_t* __restrict__ B,
                                                   const float* __restrict__ bias,
                                                   const float* __restrict__ res,
                                                   void* __restrict__ Cv,
                                                   int M, int N, int K)
{
    extern __shared__ uint32_t sm[];
    uint32_t* As = sm;                 // [2][128][36]
    uint32_t* Bs = sm + 2 * A_STAGE;   // [2][32][136]

    int tid = threadIdx.x;
    int wid = tid >> 5, lane = tid & 31;
    int gid = lane >> 2, tig = lane & 3;
    int warp_m = wid & 1, warp_n = wid >> 1;
    int bx = blockIdx.x, by = blockIdx.y;

    // per-thread cp.async coordinates (4 x 16B each for A and B)
    const uint32_t* Asrc[4];
    const uint32_t* Bsrc[4];
    uint32_t Adst[4], Bdst[4];   // smem addr within stage 0
    #pragma unroll
    for (int j = 0; j < 4; j++) {
        int ia = tid + j * 256;
        int m = ia >> 3, kq = (ia & 7) * 4;
        Asrc[j] = A + (size_t)(by * 128 + m) * K + kq;
        Adst[j] = (uint32_t)__cvta_generic_to_shared(&As[m * AS_STRIDE + kq]);
        int ib = tid + j * 256;
        int kb = ib >> 5, nq = (ib & 31) * 4;
        Bsrc[j] = B + (size_t)kb * N + bx * 128 + nq;
        Bdst[j] = (uint32_t)__cvta_generic_to_shared(&Bs[kb * BS_STRIDE + nq]);
    }

    float acc[4][4][4];
    #pragma unroll
    for (int mt = 0; mt < 4; mt++)
        #pragma unroll
        for (int nt = 0; nt < 4; nt++)
            #pragma unroll
            for (int r = 0; r < 4; r++) acc[mt][nt][r] = 0.0f;

    // prologue: stage 0
    #pragma unroll
    for (int j = 0; j < 4; j++) {
        cp16(Adst[j], Asrc[j]);
        cp16(Bdst[j], Bsrc[j]);
    }
    cp_commit();

    int nIter = K >> 5;
    for (int it = 0; it < nIter; it++) {
        int buf = it & 1;
        if (it + 1 < nIter) {
            int nb = (it + 1) & 1;
            int k0 = (it + 1) << 5;
            #pragma unroll
            for (int j = 0; j < 4; j++) {
                cp16(Adst[j] + nb * A_STAGE * 4, Asrc[j] + k0);
                cp16(Bdst[j] + nb * B_STAGE * 4, Bsrc[j] + (size_t)k0 * N);
            }
            cp_commit();
            cp_wait<1>();
        } else {
            cp_wait<0>();
        }
        __syncthreads();

        const uint32_t* Ab = As + buf * A_STAGE;
        const uint32_t* Bb = Bs + buf * B_STAGE;
        #pragma unroll
        for (int ks = 0; ks < 4; ks++) {
            int kk = ks * 8;
            uint32_t af[4][4], bf[4][2];
            #pragma unroll
            for (int mt = 0; mt < 4; mt++) {
                int m0 = warp_m * 64 + mt * 16;
                af[mt][0] = Ab[(m0 + gid    ) * AS_STRIDE + kk + tig    ];
                af[mt][1] = Ab[(m0 + gid + 8) * AS_STRIDE + kk + tig    ];
                af[mt][2] = Ab[(m0 + gid    ) * AS_STRIDE + kk + tig + 4];
                af[mt][3] = Ab[(m0 + gid + 8) * AS_STRIDE + kk + tig + 4];
            }
            #pragma unroll
            for (int nt = 0; nt < 4; nt++) {
                int n0 = warp_n * 32 + nt * 8;
                bf[nt][0] = Bb[(kk + tig    ) * BS_STRIDE + n0 + gid];
                bf[nt][1] = Bb[(kk + tig + 4) * BS_STRIDE + n0 + gid];
            }
            #pragma unroll
            for (int mt = 0; mt < 4; mt++)
                #pragma unroll
                for (int nt = 0; nt < 4; nt++)
                    mma_tf32(acc[mt][nt], af[mt], bf[nt]);
        }
        __syncthreads();
    }

    // epilogue
    #pragma unroll
    for (int mt = 0; mt < 4; mt++) {
        #pragma unroll
        for (int nt = 0; nt < 4; nt++) {
            int row0 = by * 128 + warp_m * 64 + mt * 16 + gid;
            int col  = bx * 128 + warp_n * 32 + nt * 8 + tig * 2;
            float b0 = bias[col], b1 = bias[col + 1];
            #pragma unroll
            for (int half = 0; half < 2; half++) {
                int row = row0 + half * 8;
                float v0 = acc[mt][nt][half * 2 + 0] + b0;
                float v1 = acc[mt][nt][half * 2 + 1] + b1;
                if (EPI == EPI_BIAS_GELU) {
                    v0 = 0.5f * v0 * (1.0f + erff(v0 * 0.70710678118654752f));
                    v1 = 0.5f * v1 * (1.0f + erff(v1 * 0.70710678118654752f));
                    uint2 o2 = { f2tf32(v0), f2tf32(v1) };
                    *(uint2*)((uint32_t*)Cv + (size_t)row * N + col) = o2;
                } else {
                    if (EPI == EPI_BIAS_RES) {
                        float2 rv = *(const float2*)(res + (size_t)row * N + col);
                        v0 += rv.x; v1 += rv.y;
                    }
                    float2 o2 = { v0, v1 };
                    *(float2*)((float*)Cv + (size_t)row * N + col) = o2;
                }
            }
        }
    }
}

// ---------------- Flash attention (fp32 math, tf32-rounded output) ----------------
__global__ __launch_bounds__(256) void attn_kernel(const float* __restrict__ qkv,
                                                   uint32_t* __restrict__ out)
{
    __shared__ float Qs[64][64];
    __shared__ float Ks[64][64];
    __shared__ float Vs[64][64];

    int bh = blockIdx.y;
    int b = bh >> 4, h = bh & 15;
    int q0 = blockIdx.x * 64;
    int tid = threadIdx.x;
    int tx = tid & 15, ty = tid >> 4;

    for (int i = tid; i < 64 * 16; i += 256) {
        int r = i >> 4, c = (i & 15) * 4;
        float4 v = *(const float4*)(qkv + ((size_t)(b * SEQ + q0 + r) * 3 * D_MODEL) + h * HD + c);
        Qs[c + 0][r ^ ((c + 0) & 28)] = v.x * 0.125f;
        Qs[c + 1][r ^ ((c + 1) & 28)] = v.y * 0.125f;
        Qs[c + 2][r ^ ((c + 2) & 28)] = v.z * 0.125f;
        Qs[c + 3][r ^ ((c + 3) & 28)] = v.w * 0.125f;
    }

    float o[4][4];
    float m[4], l[4];
    #pragma unroll
    for (int i = 0; i < 4; i++) {
        m[i] = -3.0e38f; l[i] = 0.0f;
        #pragma unroll
        for (int j = 0; j < 4; j++) o[i][j] = 0.0f;
    }
    __syncthreads();

    for (int kt = 0; kt <= q0; kt += 64) {
        for (int i = tid; i < 64 * 16; i += 256) {
            int r = i >> 4, c = (i & 15) * 4;
            size_t base = ((size_t)(b * SEQ + kt + r) * 3 * D_MODEL) + h * HD + c;
            float4 kv = *(const float4*)(qkv + base + D_MODEL);
            Ks[c + 0][r ^ ((c + 0) & 28)] = kv.x;
            Ks[c + 1][r ^ ((c + 1) & 28)] = kv.y;
            Ks[c + 2][r ^ ((c + 2) & 28)] = kv.z;
            Ks[c + 3][r ^ ((c + 3) & 28)] = kv.w;
            *(float4*)&Vs[r][c] = *(const float4*)(qkv + base + 2 * D_MODEL);
        }
        __syncthreads();

        float s[4][4];
        #pragma unroll
        for (int i = 0; i < 4; i++)
            #pragma unroll
            for (int j = 0; j < 4; j++) s[i][j] = 0.0f;
        #pragma unroll 16
        for (int k = 0; k < 64; k++) {
            int swz = k & 28;
            float4 qv = *(const float4*)&Qs[k][(ty * 4) ^ swz];
            float4 kv = *(const float4*)&Ks[k][(tx * 4) ^ swz];
            float qr[4] = {qv.x, qv.y, qv.z, qv.w};
            float kc[4] = {kv.x, kv.y, kv.z, kv.w};
            #pragma unroll
            for (int i = 0; i < 4; i++)
                #pragma unroll
                for (int j = 0; j < 4; j++)
                    s[i][j] = fmaf(qr[i], kc[j], s[i][j]);
        }

        if (kt == q0) {
            #pragma unroll
            for (int i = 0; i < 4; i++)
                #pragma unroll
                for (int j = 0; j < 4; j++)
                    if (tx * 4 + j > ty * 4 + i) s[i][j] = -3.0e38f;
        }

        float p[4][4];
        #pragma unroll
        for (int i = 0; i < 4; i++) {
            float tmax = fmaxf(fmaxf(s[i][0], s[i][1]), fmaxf(s[i][2], s[i][3]));
            #pragma unroll
            for (int off = 8; off > 0; off >>= 1)
                tmax = fmaxf(tmax, __shfl_xor_sync(0xFFFFFFFFu, tmax, off, 16));
            float mn = fmaxf(m[i], tmax);
            float cc = __expf(m[i] - mn);
            m[i] = mn;
            float psum = 0.0f;
            #pragma unroll
            for (int j = 0; j < 4; j++) {
                p[i][j] = __expf(s[i][j] - mn);
                psum += p[i][j];
            }
            #pragma unroll
            for (int off = 8; off > 0; off >>= 1)
                psum += __shfl_xor_sync(0xFFFFFFFFu, psum, off, 16);
            l[i] = l[i] * cc + psum;
            #pragma unroll
            for (int j = 0; j < 4; j++) o[i][j] *= cc;
        }

        __syncthreads();
        #pragma unroll
        for (int j = 0; j < 4; j++) {
            int c = tx * 4 + j;
            int swz = c & 28;
            #pragma unroll
            for (int i = 0; i < 4; i++)
                Ks[c][(ty * 4 + i) ^ swz] = p[i][j];
        }
        __syncthreads();

        #pragma unroll 16
        for (int k = 0; k < 64; k++) {
            int swz = k & 28;
            float4 pv = *(const float4*)&Ks[k][(ty * 4) ^ swz];
            float4 vv = *(const float4*)&Vs[k][tx * 4];
            float pr[4] = {pv.x, pv.y, pv.z, pv.w};
            float vd[4] = {vv.x, vv.y, vv.z, vv.w};
            #pragma unroll
            for (int i = 0; i < 4; i++)
                #pragma unroll
                for (int j = 0; j < 4; j++)
                    o[i][j] = fmaf(pr[i], vd[j], o[i][j]);
        }
        __syncthreads();
    }

    #pragma unroll
    for (int i = 0; i < 4; i++) {
        float inv = 1.0f / l[i];
        uint4 r;
        r.x = f2tf32(o[i][0] * inv); r.y = f2tf32(o[i][1] * inv);
        r.z = f2tf32(o[i][2] * inv); r.w = f2tf32(o[i][3] * inv);
        *(uint4*)(out + ((size_t)(b * SEQ + q0 + ty * 4 + i) * D_MODEL) + h * HD + tx * 4) = r;
    }
}

// ---------------- launch ----------------
extern "C" void kernel_launch(void* const* d_in, const int* in_sizes, int n_in,
                              void* d_out, int out_size)
{
    const float* x          = (const float*)d_in[0];
    const float* ln1_w      = (const float*)d_in[1];
    const float* ln1_b      = (const float*)d_in[2];
    const float* qkv_w      = (const float*)d_in[3];
    const float* qkv_b      = (const float*)d_in[4];
    const float* attn_out_w = (const float*)d_in[5];
    const float* attn_out_b = (const float*)d_in[6];
    const float* ln2_w      = (const float*)d_in[7];
    const float* ln2_b      = (const float*)d_in[8];
    const float* c_fc_w     = (const float*)d_in[9];
    const float* c_fc_b     = (const float*)d_in[10];
    const float* c_proj_w   = (const float*)d_in[11];
    const float* c_proj_b   = (const float*)d_in[12];
    float* out = (float*)d_out;

    float *XN, *QKV, *H, *HN;
    uint32_t *XNt, *Ot, *HNt, *Gt, *Wqkv, *Wproj, *Wfc, *Wpr2;
    cudaGetSymbolAddress((void**)&XN,   g_XN);
    cudaGetSymbolAddress((void**)&XNt,  g_XNt);
    cudaGetSymbolAddress((void**)&QKV,  g_QKV);
    cudaGetSymbolAddress((void**)&Ot,   g_Ot);
    cudaGetSymbolAddress((void**)&H,    g_H);
    cudaGetSymbolAddress((void**)&HN,   g_HN);
    cudaGetSymbolAddress((void**)&HNt,  g_HNt);
    cudaGetSymbolAddress((void**)&Gt,   g_Gt);
    cudaGetSymbolAddress((void**)&Wqkv, g_Wqkv);
    cudaGetSymbolAddress((void**)&Wproj,g_Wproj);
    cudaGetSymbolAddress((void**)&Wfc,  g_Wfc);
    cudaGetSymbolAddress((void**)&Wpr2, g_Wpr2);

    cudaFuncSetAttribute(mma_gemm<EPI_BIAS>,      cudaFuncAttributeMaxDynamicSharedMemorySize, GEMM_SMEM_BYTES);
    cudaFuncSetAttribute(mma_gemm<EPI_BIAS_GELU>, cudaFuncAttributeMaxDynamicSharedMemorySize, GEMM_SMEM_BYTES);
    cudaFuncSetAttribute(mma_gemm<EPI_BIAS_RES>,  cudaFuncAttributeMaxDynamicSharedMemorySize, GEMM_SMEM_BYTES);

    // weight conversions (graph-captured every replay; cheap elementwise)
    cvt_tf32_kernel<<<3 * D_MODEL * D_MODEL / 1024, 256>>>(qkv_w, Wqkv);
    cvt_tf32_kernel<<<D_MODEL * D_MODEL / 1024, 256>>>(attn_out_w, Wproj);
    cvt_tf32_kernel<<<4 * D_MODEL * D_MODEL / 1024, 256>>>(c_fc_w, Wfc);
    cvt_tf32_kernel<<<4 * D_MODEL * D_MODEL / 1024, 256>>>(c_proj_w, Wpr2);

    ln_kernel<<<ROWS, 256>>>(x, ln1_w, ln1_b, XN, XNt);

    mma_gemm<EPI_BIAS><<<dim3(3 * D_MODEL / 128, ROWS / 128), 256, GEMM_SMEM_BYTES>>>(
        XNt, Wqkv, qkv_b, nullptr, QKV, ROWS, 3 * D_MODEL, D_MODEL);

    attn_kernel<<<dim3(SEQ / 64, BATCH * NHEAD), 256>>>(QKV, Ot);

    mma_gemm<EPI_BIAS_RES><<<dim3(D_MODEL / 128, ROWS / 128), 256, GEMM_SMEM_BYTES>>>(
        Ot, Wproj, attn_out_b, XN, H, ROWS, D_MODEL, D_MODEL);

    ln_kernel<<<ROWS, 256>>>(H, ln2_w, ln2_b, HN, HNt);

    mma_gemm<EPI_BIAS_GELU><<<dim3(4 * D_MODEL / 128, ROWS / 128), 256, GEMM_SMEM_BYTES>>>(
        HNt, Wfc, c_fc_b, nullptr, Gt, ROWS, 4 * D_MODEL, D_MODEL);

    mma_gemm<EPI_BIAS_RES><<<dim3(D_MODEL / 128, ROWS / 128), 256, GEMM_SMEM_BYTES>>>(
        Gt, Wpr2, c_proj_b, HN, out, ROWS, D_MODEL, 4 * D_MODEL);
}

// round 6
// speedup vs baseline: 4.2114x; 1.4997x over previous
#include <cuda_runtime.h>
#include <math.h>
#include <stdint.h>

#define D_MODEL 1024
#define SEQ 2048
#define BATCH 2
#define NHEAD 16
#define HD 64
#define ROWS (BATCH*SEQ)   // 4096

// ---------------- scratch (static device memory; no allocation) ----------------
__device__ float    g_XN [ROWS * D_MODEL];       // ln1(x) fp32 (residual)
__device__ uint32_t g_XNt[ROWS * D_MODEL];       // ln1(x) tf32
__device__ float    g_QKV[ROWS * 3 * D_MODEL];   // qkv fp32 (attention input)
__device__ uint32_t g_Ot [ROWS * D_MODEL];       // attention out, tf32
__device__ float    g_H  [ROWS * D_MODEL];       // xn + attn_proj fp32
__device__ float    g_HN [ROWS * D_MODEL];       // ln2(h) fp32 (residual)
__device__ uint32_t g_HNt[ROWS * D_MODEL];       // ln2(h) tf32
__device__ uint32_t g_Gt [ROWS * 4 * D_MODEL];   // gelu(fc) tf32
// tf32 weight copies
__device__ uint32_t g_Wqkv [D_MODEL * 3 * D_MODEL];
__device__ uint32_t g_Wproj[D_MODEL * D_MODEL];
__device__ uint32_t g_Wfc  [D_MODEL * 4 * D_MODEL];
__device__ uint32_t g_Wpr2 [4 * D_MODEL * D_MODEL];

__device__ __forceinline__ uint32_t f2tf32(float x) {
    uint32_t r;
    asm("cvt.rna.tf32.f32 %0, %1;" : "=r"(r) : "f"(x));
    return r;
}

// ---------------- weight -> tf32 conversion ----------------
__global__ __launch_bounds__(256) void cvt_tf32_kernel(const float* __restrict__ in,
                                                       uint32_t* __restrict__ out)
{
    int i = (blockIdx.x * 256 + threadIdx.x) * 4;
    float4 v = *(const float4*)(in + i);
    uint4 u = { f2tf32(v.x), f2tf32(v.y), f2tf32(v.z), f2tf32(v.w) };
    *(uint4*)(out + i) = u;
}

// ---------------- LayerNorm (writes fp32 + tf32 copies) ----------------
__global__ __launch_bounds__(256) void ln_kernel(const float* __restrict__ x,
                                                 const float* __restrict__ w,
                                                 const float* __restrict__ b,
                                                 float* __restrict__ y,
                                                 uint32_t* __restrict__ ytf)
{
    int row = blockIdx.x;
    int t = threadIdx.x;
    const float4* xr = (const float4*)(x + (size_t)row * D_MODEL);
    float4 v = xr[t];
    float s  = v.x + v.y + v.z + v.w;
    float sq = v.x*v.x + v.y*v.y + v.z*v.z + v.w*v.w;
    #pragma unroll
    for (int o = 16; o > 0; o >>= 1) {
        s  += __shfl_xor_sync(0xFFFFFFFFu, s, o);
        sq += __shfl_xor_sync(0xFFFFFFFFu, sq, o);
    }
    __shared__ float ss[8], ssq[8];
    int wid = t >> 5, lane = t & 31;
    if (lane == 0) { ss[wid] = s; ssq[wid] = sq; }
    __syncthreads();
    if (wid == 0) {
        s  = (lane < 8) ? ss[lane]  : 0.0f;
        sq = (lane < 8) ? ssq[lane] : 0.0f;
        #pragma unroll
        for (int o = 4; o > 0; o >>= 1) {
            s  += __shfl_xor_sync(0xFFFFFFFFu, s, o);
            sq += __shfl_xor_sync(0xFFFFFFFFu, sq, o);
        }
        if (lane == 0) {
            float mu = s * (1.0f / D_MODEL);
            ss[0]  = mu;
            ssq[0] = rsqrtf(sq * (1.0f / D_MODEL) - mu * mu + 1e-5f);
        }
    }
    __syncthreads();
    float mu = ss[0], rstd = ssq[0];
    float4 wv = ((const float4*)w)[t];
    float4 bv = ((const float4*)b)[t];
    float4 r;
    r.x = (v.x - mu) * rstd * wv.x + bv.x;
    r.y = (v.y - mu) * rstd * wv.y + bv.y;
    r.z = (v.z - mu) * rstd * wv.z + bv.z;
    r.w = (v.w - mu) * rstd * wv.w + bv.w;
    ((float4*)(y + (size_t)row * D_MODEL))[t] = r;
    uint4 u = { f2tf32(r.x), f2tf32(r.y), f2tf32(r.z), f2tf32(r.w) };
    ((uint4*)(ytf + (size_t)row * D_MODEL))[t] = u;
}

// ---------------- common MMA helpers ----------------
__device__ __forceinline__ void mma_tf32(float* d, const uint32_t* a, const uint32_t* b) {
    asm volatile(
        "mma.sync.aligned.m16n8k8.row.col.f32.tf32.tf32.f32 "
        "{%0,%1,%2,%3}, {%4,%5,%6,%7}, {%8,%9}, {%0,%1,%2,%3};\n"
        : "+f"(d[0]), "+f"(d[1]), "+f"(d[2]), "+f"(d[3])
        : "r"(a[0]), "r"(a[1]), "r"(a[2]), "r"(a[3]), "r"(b[0]), "r"(b[1]));
}

__device__ __forceinline__ void cp16(uint32_t dst, const void* src) {
    asm volatile("cp.async.cg.shared.global [%0], [%1], 16;\n" :: "r"(dst), "l"(src));
}
__device__ __forceinline__ void cp_commit() {
    asm volatile("cp.async.commit_group;\n");
}
template <int N>
__device__ __forceinline__ void cp_wait() {
    asm volatile("cp.async.wait_group %0;\n" :: "n"(N));
}

// ---------------- tf32 tensor-core GEMM (cp.async 3-stage) ----------------
#define EPI_BIAS      0
#define EPI_BIAS_GELU 1
#define EPI_BIAS_RES  2

#define AS_STRIDE 36
#define BS_STRIDE 136
#define A_STAGE (128 * AS_STRIDE)
#define B_STAGE (32 * BS_STRIDE)
#define GEMM_STAGES 3
#define GEMM_SMEM_BYTES (GEMM_STAGES * (A_STAGE + B_STAGE) * 4)

template <int EPI>
__global__ __launch_bounds__(256, 2) void mma_gemm(const uint32_t* __restrict__ A,
                                                   const uint32_t* __restrict__ B,
                                                   const float* __restrict__ bias,
                                                   const float* __restrict__ res,
                                                   void* __restrict__ Cv,
                                                   int M, int N, int K)
{
    extern __shared__ uint32_t sm[];
    uint32_t* As = sm;                             // [3][128][36]
    uint32_t* Bs = sm + GEMM_STAGES * A_STAGE;     // [3][32][136]

    int tid = threadIdx.x;
    int wid = tid >> 5, lane = tid & 31;
    int gid = lane >> 2, tig = lane & 3;
    int warp_m = wid & 1, warp_n = wid >> 1;
    int bx = blockIdx.x, by = blockIdx.y;

    const uint32_t* Asrc[4];
    const uint32_t* Bsrc[4];
    uint32_t Adst[4], Bdst[4];
    #pragma unroll
    for (int j = 0; j < 4; j++) {
        int ia = tid + j * 256;
        int m = ia >> 3, kq = (ia & 7) * 4;
        Asrc[j] = A + (size_t)(by * 128 + m) * K + kq;
        Adst[j] = (uint32_t)__cvta_generic_to_shared(&As[m * AS_STRIDE + kq]);
        int ib = tid + j * 256;
        int kb = ib >> 5, nq = (ib & 31) * 4;
        Bsrc[j] = B + (size_t)kb * N + bx * 128 + nq;
        Bdst[j] = (uint32_t)__cvta_generic_to_shared(&Bs[kb * BS_STRIDE + nq]);
    }

    float acc[4][4][4];
    #pragma unroll
    for (int mt = 0; mt < 4; mt++)
        #pragma unroll
        for (int nt = 0; nt < 4; nt++)
            #pragma unroll
            for (int r = 0; r < 4; r++) acc[mt][nt][r] = 0.0f;

    int nIter = K >> 5;
    // prologue: stages 0, 1
    #pragma unroll
    for (int s = 0; s < 2; s++) {
        #pragma unroll
        for (int j = 0; j < 4; j++) {
            cp16(Adst[j] + s * A_STAGE * 4, Asrc[j] + s * 32);
            cp16(Bdst[j] + s * B_STAGE * 4, Bsrc[j] + (size_t)(s * 32) * N);
        }
        cp_commit();
    }

    for (int it = 0; it < nIter; it++) {
        if (it + 2 < nIter) {
            int sb = (it + 2) % GEMM_STAGES;
            int k0 = (it + 2) << 5;
            #pragma unroll
            for (int j = 0; j < 4; j++) {
                cp16(Adst[j] + sb * A_STAGE * 4, Asrc[j] + k0);
                cp16(Bdst[j] + sb * B_STAGE * 4, Bsrc[j] + (size_t)k0 * N);
            }
            cp_commit();
            cp_wait<2>();
        } else if (it + 1 < nIter) {
            cp_wait<1>();
        } else {
            cp_wait<0>();
        }
        __syncthreads();

        int buf = it % GEMM_STAGES;
        const uint32_t* Ab = As + buf * A_STAGE;
        const uint32_t* Bb = Bs + buf * B_STAGE;
        #pragma unroll
        for (int ks = 0; ks < 4; ks++) {
            int kk = ks * 8;
            uint32_t af[4][4], bf[4][2];
            #pragma unroll
            for (int mt = 0; mt < 4; mt++) {
                int m0 = warp_m * 64 + mt * 16;
                af[mt][0] = Ab[(m0 + gid    ) * AS_STRIDE + kk + tig    ];
                af[mt][1] = Ab[(m0 + gid + 8) * AS_STRIDE + kk + tig    ];
                af[mt][2] = Ab[(m0 + gid    ) * AS_STRIDE + kk + tig + 4];
                af[mt][3] = Ab[(m0 + gid + 8) * AS_STRIDE + kk + tig + 4];
            }
            #pragma unroll
            for (int nt = 0; nt < 4; nt++) {
                int n0 = warp_n * 32 + nt * 8;
                bf[nt][0] = Bb[(kk + tig    ) * BS_STRIDE + n0 + gid];
                bf[nt][1] = Bb[(kk + tig + 4) * BS_STRIDE + n0 + gid];
            }
            #pragma unroll
            for (int mt = 0; mt < 4; mt++)
                #pragma unroll
                for (int nt = 0; nt < 4; nt++)
                    mma_tf32(acc[mt][nt], af[mt], bf[nt]);
        }
        __syncthreads();
    }

    // epilogue
    #pragma unroll
    for (int mt = 0; mt < 4; mt++) {
        #pragma unroll
        for (int nt = 0; nt < 4; nt++) {
            int row0 = by * 128 + warp_m * 64 + mt * 16 + gid;
            int col  = bx * 128 + warp_n * 32 + nt * 8 + tig * 2;
            float b0 = bias[col], b1 = bias[col + 1];
            #pragma unroll
            for (int half = 0; half < 2; half++) {
                int row = row0 + half * 8;
                float v0 = acc[mt][nt][half * 2 + 0] + b0;
                float v1 = acc[mt][nt][half * 2 + 1] + b1;
                if (EPI == EPI_BIAS_GELU) {
                    v0 = 0.5f * v0 * (1.0f + erff(v0 * 0.70710678118654752f));
                    v1 = 0.5f * v1 * (1.0f + erff(v1 * 0.70710678118654752f));
                    uint2 o2 = { f2tf32(v0), f2tf32(v1) };
                    *(uint2*)((uint32_t*)Cv + (size_t)row * N + col) = o2;
                } else {
                    if (EPI == EPI_BIAS_RES) {
                        float2 rv = *(const float2*)(res + (size_t)row * N + col);
                        v0 += rv.x; v1 += rv.y;
                    }
                    float2 o2 = { v0, v1 };
                    *(float2*)((float*)Cv + (size_t)row * N + col) = o2;
                }
            }
        }
    }
}

// ---------------- Flash attention on tensor cores (tf32 MMA) ----------------
// Block: 128 threads = 4 warps, 64 queries (16 rows/warp). Key tiles of 64.
// Q fragments live in registers; Q smem buffer is reused for P.
#define QP_STRIDE 68
#define V_STRIDE  72
#define ATTN_SMEM ((2 * 64 * QP_STRIDE + 64 * V_STRIDE) * 4)

__global__ __launch_bounds__(128) void attn_kernel(const float* __restrict__ qkv,
                                                   uint32_t* __restrict__ out)
{
    extern __shared__ uint32_t smem_a[];
    uint32_t* QP = smem_a;                    // [64][68]: Q, then reused as P
    uint32_t* Ks = smem_a + 64 * QP_STRIDE;   // [64][68]
    uint32_t* Vs = smem_a + 2 * 64 * QP_STRIDE; // [64][72]

    int bh = blockIdx.y;
    int b = bh >> 4, h = bh & 15;
    int q0 = blockIdx.x * 64;
    int tid = threadIdx.x;
    int wid = tid >> 5, lane = tid & 31;
    int gid = lane >> 2, tig = lane & 3;
    int m0 = wid * 16;

    // load Q (pre-scaled, tf32)
    for (int i = tid; i < 64 * 16; i += 128) {
        int r = i >> 4, c = (i & 15) * 4;
        float4 v = *(const float4*)(qkv + (size_t)(b * SEQ + q0 + r) * 3 * D_MODEL + h * HD + c);
        uint4 u = { f2tf32(v.x * 0.125f), f2tf32(v.y * 0.125f),
                    f2tf32(v.z * 0.125f), f2tf32(v.w * 0.125f) };
        *(uint4*)&QP[r * QP_STRIDE + c] = u;
    }
    __syncthreads();

    // Q fragments -> registers (each warp reads only its own 16 rows)
    uint32_t qa[8][4];
    #pragma unroll
    for (int ks = 0; ks < 8; ks++) {
        int kk = ks * 8;
        qa[ks][0] = QP[(m0 + gid    ) * QP_STRIDE + kk + tig    ];
        qa[ks][1] = QP[(m0 + gid + 8) * QP_STRIDE + kk + tig    ];
        qa[ks][2] = QP[(m0 + gid    ) * QP_STRIDE + kk + tig + 4];
        qa[ks][3] = QP[(m0 + gid + 8) * QP_STRIDE + kk + tig + 4];
    }

    float o[8][4];
    #pragma unroll
    for (int nt = 0; nt < 8; nt++)
        #pragma unroll
        for (int j = 0; j < 4; j++) o[nt][j] = 0.0f;
    float ms0 = -3.0e38f, ms1 = -3.0e38f, ls0 = 0.0f, ls1 = 0.0f;

    __syncthreads();   // Q reads done before QP reused as P

    for (int kt = 0; kt <= q0; kt += 64) {
        // load K, V tiles (tf32)
        for (int i = tid; i < 64 * 16; i += 128) {
            int r = i >> 4, c = (i & 15) * 4;
            const float* base = qkv + (size_t)(b * SEQ + kt + r) * 3 * D_MODEL + h * HD + c;
            float4 kv = *(const float4*)(base + D_MODEL);
            float4 vv = *(const float4*)(base + 2 * D_MODEL);
            uint4 uk = { f2tf32(kv.x), f2tf32(kv.y), f2tf32(kv.z), f2tf32(kv.w) };
            uint4 uv = { f2tf32(vv.x), f2tf32(vv.y), f2tf32(vv.z), f2tf32(vv.w) };
            *(uint4*)&Ks[r * QP_STRIDE + c] = uk;
            *(uint4*)&Vs[r * V_STRIDE  + c] = uv;
        }
        __syncthreads();

        // S = Q @ K^T
        float sc[8][4];
        #pragma unroll
        for (int nt = 0; nt < 8; nt++)
            #pragma unroll
            for (int j = 0; j < 4; j++) sc[nt][j] = 0.0f;
        #pragma unroll
        for (int ks = 0; ks < 8; ks++) {
            int kk = ks * 8;
            #pragma unroll
            for (int nt = 0; nt < 8; nt++) {
                uint32_t bf[2] = { Ks[(nt * 8 + gid) * QP_STRIDE + kk + tig],
                                   Ks[(nt * 8 + gid) * QP_STRIDE + kk + tig + 4] };
                mma_tf32(sc[nt], qa[ks], bf);
            }
        }

        // causal mask (diagonal tile only; local row/col compare)
        if (kt == q0) {
            int r0 = m0 + gid, r1 = r0 + 8;
            #pragma unroll
            for (int nt = 0; nt < 8; nt++) {
                int c0 = nt * 8 + tig * 2;
                if (c0     > r0) sc[nt][0] = -3.0e38f;
                if (c0 + 1 > r0) sc[nt][1] = -3.0e38f;
                if (c0     > r1) sc[nt][2] = -3.0e38f;
                if (c0 + 1 > r1) sc[nt][3] = -3.0e38f;
            }
        }

        // online softmax on fragments (rows gid / gid+8; quad-lane reduce)
        float tm0 = -3.0e38f, tm1 = -3.0e38f;
        #pragma unroll
        for (int nt = 0; nt < 8; nt++) {
            tm0 = fmaxf(tm0, fmaxf(sc[nt][0], sc[nt][1]));
            tm1 = fmaxf(tm1, fmaxf(sc[nt][2], sc[nt][3]));
        }
        #pragma unroll
        for (int off = 1; off <= 2; off <<= 1) {
            tm0 = fmaxf(tm0, __shfl_xor_sync(0xFFFFFFFFu, tm0, off));
            tm1 = fmaxf(tm1, __shfl_xor_sync(0xFFFFFFFFu, tm1, off));
        }
        float mn0 = fmaxf(ms0, tm0), mn1 = fmaxf(ms1, tm1);
        float cc0 = __expf(ms0 - mn0), cc1 = __expf(ms1 - mn1);
        ms0 = mn0; ms1 = mn1;
        float ps0 = 0.0f, ps1 = 0.0f;
        #pragma unroll
        for (int nt = 0; nt < 8; nt++) {
            sc[nt][0] = __expf(sc[nt][0] - mn0); ps0 += sc[nt][0];
            sc[nt][1] = __expf(sc[nt][1] - mn0); ps0 += sc[nt][1];
            sc[nt][2] = __expf(sc[nt][2] - mn1); ps1 += sc[nt][2];
            sc[nt][3] = __expf(sc[nt][3] - mn1); ps1 += sc[nt][3];
        }
        #pragma unroll
        for (int off = 1; off <= 2; off <<= 1) {
            ps0 += __shfl_xor_sync(0xFFFFFFFFu, ps0, off);
            ps1 += __shfl_xor_sync(0xFFFFFFFFu, ps1, off);
        }
        ls0 = ls0 * cc0 + ps0;
        ls1 = ls1 * cc1 + ps1;
        #pragma unroll
        for (int nt = 0; nt < 8; nt++) {
            o[nt][0] *= cc0; o[nt][1] *= cc0;
            o[nt][2] *= cc1; o[nt][3] *= cc1;
        }

        // P -> smem (warp-private rows; QP buffer reuse)
        __syncwarp();
        #pragma unroll
        for (int nt = 0; nt < 8; nt++) {
            int c0 = nt * 8 + tig * 2;
            QP[(m0 + gid    ) * QP_STRIDE + c0    ] = f2tf32(sc[nt][0]);
            QP[(m0 + gid    ) * QP_STRIDE + c0 + 1] = f2tf32(sc[nt][1]);
            QP[(m0 + gid + 8) * QP_STRIDE + c0    ] = f2tf32(sc[nt][2]);
            QP[(m0 + gid + 8) * QP_STRIDE + c0 + 1] = f2tf32(sc[nt][3]);
        }
        __syncwarp();

        // O += P @ V
        #pragma unroll
        for (int ks = 0; ks < 8; ks++) {
            int kk = ks * 8;
            uint32_t af[4] = { QP[(m0 + gid    ) * QP_STRIDE + kk + tig    ],
                               QP[(m0 + gid + 8) * QP_STRIDE + kk + tig    ],
                               QP[(m0 + gid    ) * QP_STRIDE + kk + tig + 4],
                               QP[(m0 + gid + 8) * QP_STRIDE + kk + tig + 4] };
            #pragma unroll
            for (int nt = 0; nt < 8; nt++) {
                uint32_t bf[2] = { Vs[(kk + tig    ) * V_STRIDE + nt * 8 + gid],
                                   Vs[(kk + tig + 4) * V_STRIDE + nt * 8 + gid] };
                mma_tf32(o[nt], af, bf);
            }
        }
        __syncthreads();   // before next K/V tile overwrites smem
    }

    // epilogue: normalize, tf32-round, store
    float inv0 = 1.0f / ls0, inv1 = 1.0f / ls1;
    int row0 = b * SEQ + q0 + m0 + gid;
    int row1 = row0 + 8;
    #pragma unroll
    for (int nt = 0; nt < 8; nt++) {
        int col = h * HD + nt * 8 + tig * 2;
        out[(size_t)row0 * D_MODEL + col    ] = f2tf32(o[nt][0] * inv0);
        out[(size_t)row0 * D_MODEL + col + 1] = f2tf32(o[nt][1] * inv0);
        out[(size_t)row1 * D_MODEL + col    ] = f2tf32(o[nt][2] * inv1);
        out[(size_t)row1 * D_MODEL + col + 1] = f2tf32(o[nt][3] * inv1);
    }
}

// ---------------- launch ----------------
extern "C" void kernel_launch(void* const* d_in, const int* in_sizes, int n_in,
                              void* d_out, int out_size)
{
    const float* x          = (const float*)d_in[0];
    const float* ln1_w      = (const float*)d_in[1];
    const float* ln1_b      = (const float*)d_in[2];
    const float* qkv_w      = (const float*)d_in[3];
    const float* qkv_b      = (const float*)d_in[4];
    const float* attn_out_w = (const float*)d_in[5];
    const float* attn_out_b = (const float*)d_in[6];
    const float* ln2_w      = (const float*)d_in[7];
    const float* ln2_b      = (const float*)d_in[8];
    const float* c_fc_w     = (const float*)d_in[9];
    const float* c_fc_b     = (const float*)d_in[10];
    const float* c_proj_w   = (const float*)d_in[11];
    const float* c_proj_b   = (const float*)d_in[12];
    float* out = (float*)d_out;

    float *XN, *QKV, *H, *HN;
    uint32_t *XNt, *Ot, *HNt, *Gt, *Wqkv, *Wproj, *Wfc, *Wpr2;
    cudaGetSymbolAddress((void**)&XN,   g_XN);
    cudaGetSymbolAddress((void**)&XNt,  g_XNt);
    cudaGetSymbolAddress((void**)&QKV,  g_QKV);
    cudaGetSymbolAddress((void**)&Ot,   g_Ot);
    cudaGetSymbolAddress((void**)&H,    g_H);
    cudaGetSymbolAddress((void**)&HN,   g_HN);
    cudaGetSymbolAddress((void**)&HNt,  g_HNt);
    cudaGetSymbolAddress((void**)&Gt,   g_Gt);
    cudaGetSymbolAddress((void**)&Wqkv, g_Wqkv);
    cudaGetSymbolAddress((void**)&Wproj,g_Wproj);
    cudaGetSymbolAddress((void**)&Wfc,  g_Wfc);
    cudaGetSymbolAddress((void**)&Wpr2, g_Wpr2);

    cudaFuncSetAttribute(mma_gemm<EPI_BIAS>,      cudaFuncAttributeMaxDynamicSharedMemorySize, GEMM_SMEM_BYTES);
    cudaFuncSetAttribute(mma_gemm<EPI_BIAS_GELU>, cudaFuncAttributeMaxDynamicSharedMemorySize, GEMM_SMEM_BYTES);
    cudaFuncSetAttribute(mma_gemm<EPI_BIAS_RES>,  cudaFuncAttributeMaxDynamicSharedMemorySize, GEMM_SMEM_BYTES);
    cudaFuncSetAttribute(attn_kernel,             cudaFuncAttributeMaxDynamicSharedMemorySize, ATTN_SMEM);

    // weight conversions
    cvt_tf32_kernel<<<3 * D_MODEL * D_MODEL / 1024, 256>>>(qkv_w, Wqkv);
    cvt_tf32_kernel<<<D_MODEL * D_MODEL / 1024, 256>>>(attn_out_w, Wproj);
    cvt_tf32_kernel<<<4 * D_MODEL * D_MODEL / 1024, 256>>>(c_fc_w, Wfc);
    cvt_tf32_kernel<<<4 * D_MODEL * D_MODEL / 1024, 256>>>(c_proj_w, Wpr2);

    ln_kernel<<<ROWS, 256>>>(x, ln1_w, ln1_b, XN, XNt);

    mma_gemm<EPI_BIAS><<<dim3(3 * D_MODEL / 128, ROWS / 128), 256, GEMM_SMEM_BYTES>>>(
        XNt, Wqkv, qkv_b, nullptr, QKV, ROWS, 3 * D_MODEL, D_MODEL);

    attn_kernel<<<dim3(SEQ / 64, BATCH * NHEAD), 128, ATTN_SMEM>>>(QKV, Ot);

    mma_gemm<EPI_BIAS_RES><<<dim3(D_MODEL / 128, ROWS / 128), 256, GEMM_SMEM_BYTES>>>(
        Ot, Wproj, attn_out_b, XN, H, ROWS, D_MODEL, D_MODEL);

    ln_kernel<<<ROWS, 256>>>(H, ln2_w, ln2_b, HN, HNt);

    mma_gemm<EPI_BIAS_GELU><<<dim3(4 * D_MODEL / 128, ROWS / 128), 256, GEMM_SMEM_BYTES>>>(
        HNt, Wfc, c_fc_b, nullptr, Gt, ROWS, 4 * D_MODEL, D_MODEL);

    mma_gemm<EPI_BIAS_RES><<<dim3(D_MODEL / 128, ROWS / 128), 256, GEMM_SMEM_BYTES>>>(
        Gt, Wpr2, c_proj_b, HN, out, ROWS, D_MODEL, 4 * D_MODEL);
}

// round 8
// speedup vs baseline: 5.5460x; 1.3169x over previous
#include <cuda_runtime.h>
#include <cuda_fp16.h>
#include <math.h>
#include <stdint.h>

#define D_MODEL 1024
#define SEQ 2048
#define BATCH 2
#define NHEAD 16
#define HD 64
#define ROWS (BATCH*SEQ)   // 4096

// ---------------- scratch (static device memory; no allocation) ----------------
__device__ float  g_XN [ROWS * D_MODEL];       // ln1(x) fp32 (residual)
__device__ __half g_XNh[ROWS * D_MODEL];       // ln1(x) fp16
__device__ float  g_QKV[ROWS * 3 * D_MODEL];   // qkv fp32 (attention input)
__device__ __half g_Oh [ROWS * D_MODEL];       // attention out fp16
__device__ float  g_H  [ROWS * D_MODEL];       // xn + attn_proj fp32
__device__ float  g_HN [ROWS * D_MODEL];       // ln2(h) fp32 (residual)
__device__ __half g_HNh[ROWS * D_MODEL];       // ln2(h) fp16
__device__ __half g_Gh [ROWS * 4 * D_MODEL];   // gelu(fc) fp16
// fp16 weight copies, TRANSPOSED to [N][K]
__device__ __half g_Wqkv [3 * D_MODEL * D_MODEL];
__device__ __half g_Wproj[D_MODEL * D_MODEL];
__device__ __half g_Wfc  [4 * D_MODEL * D_MODEL];
__device__ __half g_Wpr2 [D_MODEL * 4 * D_MODEL];

__device__ __forceinline__ uint32_t f2tf32(float x) {
    uint32_t r;
    asm("cvt.rna.tf32.f32 %0, %1;" : "=r"(r) : "f"(x));
    return r;
}

// ---------------- weight -> fp16 transpose ([K][N] fp32 -> [N][K] fp16) ----------------
__global__ __launch_bounds__(256) void cvt_t_kernel(const float* __restrict__ W,
                                                    __half* __restrict__ Wt,
                                                    int K, int N)
{
    __shared__ float tile[32][33];
    int n0 = blockIdx.x * 32, k0 = blockIdx.y * 32;
    int tx = threadIdx.x & 31, ty = threadIdx.x >> 5;   // 32x8
    #pragma unroll
    for (int j = 0; j < 4; j++) {
        int k = k0 + ty + j * 8;
        tile[ty + j * 8][tx] = W[(size_t)k * N + n0 + tx];
    }
    __syncthreads();
    #pragma unroll
    for (int j = 0; j < 4; j++) {
        int n = n0 + ty + j * 8;
        Wt[(size_t)n * K + k0 + tx] = __float2half(tile[tx][ty + j * 8]);
    }
}

// ---------------- LayerNorm (writes fp32 + fp16 copies) ----------------
__global__ __launch_bounds__(256) void ln_kernel(const float* __restrict__ x,
                                                 const float* __restrict__ w,
                                                 const float* __restrict__ b,
                                                 float* __restrict__ y,
                                                 __half* __restrict__ yh)
{
    int row = blockIdx.x;
    int t = threadIdx.x;
    const float4* xr = (const float4*)(x + (size_t)row * D_MODEL);
    float4 v = xr[t];
    float s  = v.x + v.y + v.z + v.w;
    float sq = v.x*v.x + v.y*v.y + v.z*v.z + v.w*v.w;
    #pragma unroll
    for (int o = 16; o > 0; o >>= 1) {
        s  += __shfl_xor_sync(0xFFFFFFFFu, s, o);
        sq += __shfl_xor_sync(0xFFFFFFFFu, sq, o);
    }
    __shared__ float ss[8], ssq[8];
    int wid = t >> 5, lane = t & 31;
    if (lane == 0) { ss[wid] = s; ssq[wid] = sq; }
    __syncthreads();
    if (wid == 0) {
        s  = (lane < 8) ? ss[lane]  : 0.0f;
        sq = (lane < 8) ? ssq[lane] : 0.0f;
        #pragma unroll
        for (int o = 4; o > 0; o >>= 1) {
            s  += __shfl_xor_sync(0xFFFFFFFFu, s, o);
            sq += __shfl_xor_sync(0xFFFFFFFFu, sq, o);
        }
        if (lane == 0) {
            float mu = s * (1.0f / D_MODEL);
            ss[0]  = mu;
            ssq[0] = rsqrtf(sq * (1.0f / D_MODEL) - mu * mu + 1e-5f);
        }
    }
    __syncthreads();
    float mu = ss[0], rstd = ssq[0];
    float4 wv = ((const float4*)w)[t];
    float4 bv = ((const float4*)b)[t];
    float4 r;
    r.x = (v.x - mu) * rstd * wv.x + bv.x;
    r.y = (v.y - mu) * rstd * wv.y + bv.y;
    r.z = (v.z - mu) * rstd * wv.z + bv.z;
    r.w = (v.w - mu) * rstd * wv.w + bv.w;
    ((float4*)(y + (size_t)row * D_MODEL))[t] = r;
    __half2 h0 = __floats2half2_rn(r.x, r.y);
    __half2 h1 = __floats2half2_rn(r.z, r.w);
    uint2 u = { *(uint32_t*)&h0, *(uint32_t*)&h1 };
    *(uint2*)(yh + (size_t)row * D_MODEL + t * 4) = u;
}

// ---------------- MMA helpers ----------------
__device__ __forceinline__ void mma_f16(float* d, const uint32_t* a, const uint32_t* b) {
    asm volatile(
        "mma.sync.aligned.m16n8k16.row.col.f32.f16.f16.f32 "
        "{%0,%1,%2,%3}, {%4,%5,%6,%7}, {%8,%9}, {%0,%1,%2,%3};\n"
        : "+f"(d[0]), "+f"(d[1]), "+f"(d[2]), "+f"(d[3])
        : "r"(a[0]), "r"(a[1]), "r"(a[2]), "r"(a[3]), "r"(b[0]), "r"(b[1]));
}
__device__ __forceinline__ void mma_tf32(float* d, const uint32_t* a, const uint32_t* b) {
    asm volatile(
        "mma.sync.aligned.m16n8k8.row.col.f32.tf32.tf32.f32 "
        "{%0,%1,%2,%3}, {%4,%5,%6,%7}, {%8,%9}, {%0,%1,%2,%3};\n"
        : "+f"(d[0]), "+f"(d[1]), "+f"(d[2]), "+f"(d[3])
        : "r"(a[0]), "r"(a[1]), "r"(a[2]), "r"(a[3]), "r"(b[0]), "r"(b[1]));
}
__device__ __forceinline__ void cp16(uint32_t dst, const void* src) {
    asm volatile("cp.async.cg.shared.global [%0], [%1], 16;\n" :: "r"(dst), "l"(src));
}
__device__ __forceinline__ void cp_commit() {
    asm volatile("cp.async.commit_group;\n");
}
template <int N>
__device__ __forceinline__ void cp_wait() {
    asm volatile("cp.async.wait_group %0;\n" :: "n"(N));
}

// ---------------- fp16 tensor-core GEMM (cp.async 3-stage) ----------------
// C[M,N] = epi(A[M,K] @ Bt[N,K]^T + bias, res). A row-major fp16, Bt = W^T fp16.
// Block 128x128, BK=32. 256 thr = 8 warps (2m x 4n), warp 64x32 via m16n8k16.
// smem rows: 16 half2 payload + 4 pad = stride 20 words (gid*20+tig: bank perm).
#define EPI_BIAS      0
#define EPI_BIAS_GELU 1
#define EPI_BIAS_RES  2

#define HS_STRIDE 20
#define H_STAGE (128 * HS_STRIDE)      // uint32 words per matrix per stage
#define GEMM_STAGES 3
#define GEMM_SMEM_BYTES (GEMM_STAGES * 2 * H_STAGE * 4)

template <int EPI>
__global__ __launch_bounds__(256, 2) void mma_gemm(const __half* __restrict__ A,
                                                   const __half* __restrict__ Bt,
                                                   const float* __restrict__ bias,
                                                   const float* __restrict__ res,
                                                   void* __restrict__ Cv,
                                                   int M, int N, int K)
{
    extern __shared__ uint32_t sm[];
    uint32_t* As = sm;                          // [3][128][20]
    uint32_t* Bs = sm + GEMM_STAGES * H_STAGE;  // [3][128][20]

    int tid = threadIdx.x;
    int wid = tid >> 5, lane = tid & 31;
    int gid = lane >> 2, tig = lane & 3;
    int warp_m = wid & 1, warp_n = wid >> 1;
    int bx = blockIdx.x, by = blockIdx.y;

    // per-thread cp.async coords: 2 x 16B per matrix per stage
    const __half* Asrc[2];
    const __half* Bsrc[2];
    uint32_t Adst[2], Bdst[2];
    #pragma unroll
    for (int j = 0; j < 2; j++) {
        int q = tid + j * 256;
        int r = q >> 2, c = q & 3;            // row 0..127, 16B unit 0..3
        Asrc[j] = A  + (size_t)(by * 128 + r) * K + c * 8;
        Bsrc[j] = Bt + (size_t)(bx * 128 + r) * K + c * 8;
        Adst[j] = (uint32_t)__cvta_generic_to_shared(&As[r * HS_STRIDE + c * 4]);
        Bdst[j] = (uint32_t)__cvta_generic_to_shared(&Bs[r * HS_STRIDE + c * 4]);
    }

    float acc[4][4][4];
    #pragma unroll
    for (int mt = 0; mt < 4; mt++)
        #pragma unroll
        for (int nt = 0; nt < 4; nt++)
            #pragma unroll
            for (int r = 0; r < 4; r++) acc[mt][nt][r] = 0.0f;

    int nIter = K >> 5;
    #pragma unroll
    for (int s = 0; s < 2; s++) {
        #pragma unroll
        for (int j = 0; j < 2; j++) {
            cp16(Adst[j] + s * H_STAGE * 4, Asrc[j] + s * 32);
            cp16(Bdst[j] + s * H_STAGE * 4, Bsrc[j] + s * 32);
        }
        cp_commit();
    }

    for (int it = 0; it < nIter; it++) {
        if (it + 2 < nIter) {
            int sb = (it + 2) % GEMM_STAGES;
            int k0 = (it + 2) << 5;
            #pragma unroll
            for (int j = 0; j < 2; j++) {
                cp16(Adst[j] + sb * H_STAGE * 4, Asrc[j] + k0);
                cp16(Bdst[j] + sb * H_STAGE * 4, Bsrc[j] + k0);
            }
            cp_commit();
            cp_wait<2>();
        } else if (it + 1 < nIter) {
            cp_wait<1>();
        } else {
            cp_wait<0>();
        }
        __syncthreads();

        int buf = it % GEMM_STAGES;
        const uint32_t* Ab = As + buf * H_STAGE;
        const uint32_t* Bb = Bs + buf * H_STAGE;
        #pragma unroll
        for (int ks = 0; ks < 2; ks++) {        // two k16 steps per 32-chunk
            int kk = ks * 8;                    // half2-word offset
            uint32_t af[4][4], bf[4][2];
            #pragma unroll
            for (int mt = 0; mt < 4; mt++) {
                int m0 = warp_m * 64 + mt * 16;
                af[mt][0] = Ab[(m0 + gid    ) * HS_STRIDE + kk + tig    ];
                af[mt][1] = Ab[(m0 + gid + 8) * HS_STRIDE + kk + tig    ];
                af[mt][2] = Ab[(m0 + gid    ) * HS_STRIDE + kk + tig + 4];
                af[mt][3] = Ab[(m0 + gid + 8) * HS_STRIDE + kk + tig + 4];
            }
            #pragma unroll
            for (int nt = 0; nt < 4; nt++) {
                int n0 = warp_n * 32 + nt * 8;
                bf[nt][0] = Bb[(n0 + gid) * HS_STRIDE + kk + tig    ];
                bf[nt][1] = Bb[(n0 + gid) * HS_STRIDE + kk + tig + 4];
            }
            #pragma unroll
            for (int mt = 0; mt < 4; mt++)
                #pragma unroll
                for (int nt = 0; nt < 4; nt++)
                    mma_f16(acc[mt][nt], af[mt], bf[nt]);
        }
        __syncthreads();
    }

    // epilogue: c0,c1 -> (row gid, col 2tig..+1); c2,c3 -> row gid+8
    #pragma unroll
    for (int mt = 0; mt < 4; mt++) {
        #pragma unroll
        for (int nt = 0; nt < 4; nt++) {
            int row0 = by * 128 + warp_m * 64 + mt * 16 + gid;
            int col  = bx * 128 + warp_n * 32 + nt * 8 + tig * 2;
            float b0 = bias[col], b1 = bias[col + 1];
            #pragma unroll
            for (int half_i = 0; half_i < 2; half_i++) {
                int row = row0 + half_i * 8;
                float v0 = acc[mt][nt][half_i * 2 + 0] + b0;
                float v1 = acc[mt][nt][half_i * 2 + 1] + b1;
                if (EPI == EPI_BIAS_GELU) {
                    v0 = 0.5f * v0 * (1.0f + erff(v0 * 0.70710678118654752f));
                    v1 = 0.5f * v1 * (1.0f + erff(v1 * 0.70710678118654752f));
                    __half2 hv = __floats2half2_rn(v0, v1);
                    *(__half2*)((__half*)Cv + (size_t)row * N + col) = hv;
                } else {
                    if (EPI == EPI_BIAS_RES) {
                        float2 rv = *(const float2*)(res + (size_t)row * N + col);
                        v0 += rv.x; v1 += rv.y;
                    }
                    float2 o2 = { v0, v1 };
                    *(float2*)((float*)Cv + (size_t)row * N + col) = o2;
                }
            }
        }
    }
}

// ---------------- Flash attention on tensor cores (tf32 mma.sync) ----------------
#define QP_STRIDE 68
#define V_STRIDE  72
#define ATTN_SMEM ((2 * 64 * QP_STRIDE + 64 * V_STRIDE) * 4)

__global__ __launch_bounds__(128) void attn_kernel(const float* __restrict__ qkv,
                                                   __half* __restrict__ out)
{
    extern __shared__ uint32_t smem_a[];
    uint32_t* QP = smem_a;
    uint32_t* Ks = smem_a + 64 * QP_STRIDE;
    uint32_t* Vs = smem_a + 2 * 64 * QP_STRIDE;

    int bh = blockIdx.y;
    int b = bh >> 4, h = bh & 15;
    int q0 = blockIdx.x * 64;
    int tid = threadIdx.x;
    int wid = tid >> 5, lane = tid & 31;
    int gid = lane >> 2, tig = lane & 3;
    int m0 = wid * 16;

    for (int i = tid; i < 64 * 16; i += 128) {
        int r = i >> 4, c = (i & 15) * 4;
        float4 v = *(const float4*)(qkv + (size_t)(b * SEQ + q0 + r) * 3 * D_MODEL + h * HD + c);
        uint4 u = { f2tf32(v.x * 0.125f), f2tf32(v.y * 0.125f),
                    f2tf32(v.z * 0.125f), f2tf32(v.w * 0.125f) };
        *(uint4*)&QP[r * QP_STRIDE + c] = u;
    }
    __syncthreads();

    uint32_t qa[8][4];
    #pragma unroll
    for (int ks = 0; ks < 8; ks++) {
        int kk = ks * 8;
        qa[ks][0] = QP[(m0 + gid    ) * QP_STRIDE + kk + tig    ];
        qa[ks][1] = QP[(m0 + gid + 8) * QP_STRIDE + kk + tig    ];
        qa[ks][2] = QP[(m0 + gid    ) * QP_STRIDE + kk + tig + 4];
        qa[ks][3] = QP[(m0 + gid + 8) * QP_STRIDE + kk + tig + 4];
    }

    float o[8][4];
    #pragma unroll
    for (int nt = 0; nt < 8; nt++)
        #pragma unroll
        for (int j = 0; j < 4; j++) o[nt][j] = 0.0f;
    float ms0 = -3.0e38f, ms1 = -3.0e38f, ls0 = 0.0f, ls1 = 0.0f;

    __syncthreads();

    for (int kt = 0; kt <= q0; kt += 64) {
        for (int i = tid; i < 64 * 16; i += 128) {
            int r = i >> 4, c = (i & 15) * 4;
            const float* base = qkv + (size_t)(b * SEQ + kt + r) * 3 * D_MODEL + h * HD + c;
            float4 kv = *(const float4*)(base + D_MODEL);
            float4 vv = *(const float4*)(base + 2 * D_MODEL);
            uint4 uk = { f2tf32(kv.x), f2tf32(kv.y), f2tf32(kv.z), f2tf32(kv.w) };
            uint4 uv = { f2tf32(vv.x), f2tf32(vv.y), f2tf32(vv.z), f2tf32(vv.w) };
            *(uint4*)&Ks[r * QP_STRIDE + c] = uk;
            *(uint4*)&Vs[r * V_STRIDE  + c] = uv;
        }
        __syncthreads();

        float sc[8][4];
        #pragma unroll
        for (int nt = 0; nt < 8; nt++)
            #pragma unroll
            for (int j = 0; j < 4; j++) sc[nt][j] = 0.0f;
        #pragma unroll
        for (int ks = 0; ks < 8; ks++) {
            int kk = ks * 8;
            #pragma unroll
            for (int nt = 0; nt < 8; nt++) {
                uint32_t bf[2] = { Ks[(nt * 8 + gid) * QP_STRIDE + kk + tig],
                                   Ks[(nt * 8 + gid) * QP_STRIDE + kk + tig + 4] };
                mma_tf32(sc[nt], qa[ks], bf);
            }
        }

        if (kt == q0) {
            int r0 = m0 + gid, r1 = r0 + 8;
            #pragma unroll
            for (int nt = 0; nt < 8; nt++) {
                int c0 = nt * 8 + tig * 2;
                if (c0     > r0) sc[nt][0] = -3.0e38f;
                if (c0 + 1 > r0) sc[nt][1] = -3.0e38f;
                if (c0     > r1) sc[nt][2] = -3.0e38f;
                if (c0 + 1 > r1) sc[nt][3] = -3.0e38f;
            }
        }

        float tm0 = -3.0e38f, tm1 = -3.0e38f;
        #pragma unroll
        for (int nt = 0; nt < 8; nt++) {
            tm0 = fmaxf(tm0, fmaxf(sc[nt][0], sc[nt][1]));
            tm1 = fmaxf(tm1, fmaxf(sc[nt][2], sc[nt][3]));
        }
        #pragma unroll
        for (int off = 1; off <= 2; off <<= 1) {
            tm0 = fmaxf(tm0, __shfl_xor_sync(0xFFFFFFFFu, tm0, off));
            tm1 = fmaxf(tm1, __shfl_xor_sync(0xFFFFFFFFu, tm1, off));
        }
        float mn0 = fmaxf(ms0, tm0), mn1 = fmaxf(ms1, tm1);
        float cc0 = __expf(ms0 - mn0), cc1 = __expf(ms1 - mn1);
        ms0 = mn0; ms1 = mn1;
        float ps0 = 0.0f, ps1 = 0.0f;
        #pragma unroll
        for (int nt = 0; nt < 8; nt++) {
            sc[nt][0] = __expf(sc[nt][0] - mn0); ps0 += sc[nt][0];
            sc[nt][1] = __expf(sc[nt][1] - mn0); ps0 += sc[nt][1];
            sc[nt][2] = __expf(sc[nt][2] - mn1); ps1 += sc[nt][2];
            sc[nt][3] = __expf(sc[nt][3] - mn1); ps1 += sc[nt][3];
        }
        #pragma unroll
        for (int off = 1; off <= 2; off <<= 1) {
            ps0 += __shfl_xor_sync(0xFFFFFFFFu, ps0, off);
            ps1 += __shfl_xor_sync(0xFFFFFFFFu, ps1, off);
        }
        ls0 = ls0 * cc0 + ps0;
        ls1 = ls1 * cc1 + ps1;
        #pragma unroll
        for (int nt = 0; nt < 8; nt++) {
            o[nt][0] *= cc0; o[nt][1] *= cc0;
            o[nt][2] *= cc1; o[nt][3] *= cc1;
        }

        __syncwarp();
        #pragma unroll
        for (int nt = 0; nt < 8; nt++) {
            int c0 = nt * 8 + tig * 2;
            QP[(m0 + gid    ) * QP_STRIDE + c0    ] = f2tf32(sc[nt][0]);
            QP[(m0 + gid    ) * QP_STRIDE + c0 + 1] = f2tf32(sc[nt][1]);
            QP[(m0 + gid + 8) * QP_STRIDE + c0    ] = f2tf32(sc[nt][2]);
            QP[(m0 + gid + 8) * QP_STRIDE + c0 + 1] = f2tf32(sc[nt][3]);
        }
        __syncwarp();

        #pragma unroll
        for (int ks = 0; ks < 8; ks++) {
            int kk = ks * 8;
            uint32_t af[4] = { QP[(m0 + gid    ) * QP_STRIDE + kk + tig    ],
                               QP[(m0 + gid + 8) * QP_STRIDE + kk + tig    ],
                               QP[(m0 + gid    ) * QP_STRIDE + kk + tig + 4],
                               QP[(m0 + gid + 8) * QP_STRIDE + kk + tig + 4] };
            #pragma unroll
            for (int nt = 0; nt < 8; nt++) {
                uint32_t bf[2] = { Vs[(kk + tig    ) * V_STRIDE + nt * 8 + gid],
                                   Vs[(kk + tig + 4) * V_STRIDE + nt * 8 + gid] };
                mma_tf32(o[nt], af, bf);
            }
        }
        __syncthreads();
    }

    float inv0 = 1.0f / ls0, inv1 = 1.0f / ls1;
    int row0 = b * SEQ + q0 + m0 + gid;
    int row1 = row0 + 8;
    #pragma unroll
    for (int nt = 0; nt < 8; nt++) {
        int col = h * HD + nt * 8 + tig * 2;
        *(__half2*)(out + (size_t)row0 * D_MODEL + col) = __floats2half2_rn(o[nt][0] * inv0, o[nt][1] * inv0);
        *(__half2*)(out + (size_t)row1 * D_MODEL + col) = __floats2half2_rn(o[nt][2] * inv1, o[nt][3] * inv1);
    }
}

// ---------------- launch ----------------
extern "C" void kernel_launch(void* const* d_in, const int* in_sizes, int n_in,
                              void* d_out, int out_size)
{
    const float* x          = (const float*)d_in[0];
    const float* ln1_w      = (const float*)d_in[1];
    const float* ln1_b      = (const float*)d_in[2];
    const float* qkv_w      = (const float*)d_in[3];
    const float* qkv_b      = (const float*)d_in[4];
    const float* attn_out_w = (const float*)d_in[5];
    const float* attn_out_b = (const float*)d_in[6];
    const float* ln2_w      = (const float*)d_in[7];
    const float* ln2_b      = (const float*)d_in[8];
    const float* c_fc_w     = (const float*)d_in[9];
    const float* c_fc_b     = (const float*)d_in[10];
    const float* c_proj_w   = (const float*)d_in[11];
    const float* c_proj_b   = (const float*)d_in[12];
    float* out = (float*)d_out;

    float *XN, *QKV, *H, *HN;
    __half *XNh, *Oh, *HNh, *Gh, *Wqkv, *Wproj, *Wfc, *Wpr2;
    cudaGetSymbolAddress((void**)&XN,   g_XN);
    cudaGetSymbolAddress((void**)&XNh,  g_XNh);
    cudaGetSymbolAddress((void**)&QKV,  g_QKV);
    cudaGetSymbolAddress((void**)&Oh,   g_Oh);
    cudaGetSymbolAddress((void**)&H,    g_H);
    cudaGetSymbolAddress((void**)&HN,   g_HN);
    cudaGetSymbolAddress((void**)&HNh,  g_HNh);
    cudaGetSymbolAddress((void**)&Gh,   g_Gh);
    cudaGetSymbolAddress((void**)&Wqkv, g_Wqkv);
    cudaGetSymbolAddress((void**)&Wproj,g_Wproj);
    cudaGetSymbolAddress((void**)&Wfc,  g_Wfc);
    cudaGetSymbolAddress((void**)&Wpr2, g_Wpr2);

    cudaFuncSetAttribute(mma_gemm<EPI_BIAS>,      cudaFuncAttributeMaxDynamicSharedMemorySize, GEMM_SMEM_BYTES);
    cudaFuncSetAttribute(mma_gemm<EPI_BIAS_GELU>, cudaFuncAttributeMaxDynamicSharedMemorySize, GEMM_SMEM_BYTES);
    cudaFuncSetAttribute(mma_gemm<EPI_BIAS_RES>,  cudaFuncAttributeMaxDynamicSharedMemorySize, GEMM_SMEM_BYTES);
    cudaFuncSetAttribute(attn_kernel,             cudaFuncAttributeMaxDynamicSharedMemorySize, ATTN_SMEM);

    // weight transposes -> [N][K] fp16
    cvt_t_kernel<<<dim3(3 * D_MODEL / 32, D_MODEL / 32), 256>>>(qkv_w, Wqkv, D_MODEL, 3 * D_MODEL);
    cvt_t_kernel<<<dim3(D_MODEL / 32, D_MODEL / 32), 256>>>(attn_out_w, Wproj, D_MODEL, D_MODEL);
    cvt_t_kernel<<<dim3(4 * D_MODEL / 32, D_MODEL / 32), 256>>>(c_fc_w, Wfc, D_MODEL, 4 * D_MODEL);
    cvt_t_kernel<<<dim3(D_MODEL / 32, 4 * D_MODEL / 32), 256>>>(c_proj_w, Wpr2, 4 * D_MODEL, D_MODEL);

    ln_kernel<<<ROWS, 256>>>(x, ln1_w, ln1_b, XN, XNh);

    mma_gemm<EPI_BIAS><<<dim3(3 * D_MODEL / 128, ROWS / 128), 256, GEMM_SMEM_BYTES>>>(
        XNh, Wqkv, qkv_b, nullptr, QKV, ROWS, 3 * D_MODEL, D_MODEL);

    attn_kernel<<<dim3(SEQ / 64, BATCH * NHEAD), 128, ATTN_SMEM>>>(QKV, Oh);

    mma_gemm<EPI_BIAS_RES><<<dim3(D_MODEL / 128, ROWS / 128), 256, GEMM_SMEM_BYTES>>>(
        Oh, Wproj, attn_out_b, XN, H, ROWS, D_MODEL, D_MODEL);

    ln_kernel<<<ROWS, 256>>>(H, ln2_w, ln2_b, HN, HNh);

    mma_gemm<EPI_BIAS_GELU><<<dim3(4 * D_MODEL / 128, ROWS / 128), 256, GEMM_SMEM_BYTES>>>(
        HNh, Wfc, c_fc_b, nullptr, Gh, ROWS, 4 * D_MODEL, D_MODEL);

    mma_gemm<EPI_BIAS_RES><<<dim3(D_MODEL / 128, ROWS / 128), 256, GEMM_SMEM_BYTES>>>(
        Gh, Wpr2, c_proj_b, HN, out, ROWS, D_MODEL, 4 * D_MODEL);
}

// round 9
// speedup vs baseline: 5.8478x; 1.0544x over previous
#include <cuda_runtime.h>
#include <cuda_fp16.h>
#include <math.h>
#include <stdint.h>

#define D_MODEL 1024
#define SEQ 2048
#define BATCH 2
#define NHEAD 16
#define HD 64
#define ROWS (BATCH*SEQ)   // 4096

// ---------------- scratch ----------------
__device__ float  g_XN [ROWS * D_MODEL];
__device__ __half g_XNh[ROWS * D_MODEL];
__device__ float  g_QKV[ROWS * 3 * D_MODEL];
__device__ __half g_Oh [ROWS * D_MODEL];
__device__ float  g_H  [ROWS * D_MODEL];
__device__ float  g_HN [ROWS * D_MODEL];
__device__ __half g_HNh[ROWS * D_MODEL];
__device__ __half g_Gh [ROWS * 4 * D_MODEL];
__device__ __half g_Wqkv [3 * D_MODEL * D_MODEL];
__device__ __half g_Wproj[D_MODEL * D_MODEL];
__device__ __half g_Wfc  [4 * D_MODEL * D_MODEL];
__device__ __half g_Wpr2 [D_MODEL * 4 * D_MODEL];

__device__ __forceinline__ uint32_t f2tf32(float x) {
    uint32_t r;
    asm("cvt.rna.tf32.f32 %0, %1;" : "=r"(r) : "f"(x));
    return r;
}

// ---------------- weight -> fp16 transpose ----------------
__global__ __launch_bounds__(256) void cvt_t_kernel(const float* __restrict__ W,
                                                    __half* __restrict__ Wt,
                                                    int K, int N)
{
    __shared__ float tile[32][33];
    int n0 = blockIdx.x * 32, k0 = blockIdx.y * 32;
    int tx = threadIdx.x & 31, ty = threadIdx.x >> 5;
    #pragma unroll
    for (int j = 0; j < 4; j++) {
        int k = k0 + ty + j * 8;
        tile[ty + j * 8][tx] = W[(size_t)k * N + n0 + tx];
    }
    __syncthreads();
    #pragma unroll
    for (int j = 0; j < 4; j++) {
        int n = n0 + ty + j * 8;
        Wt[(size_t)n * K + k0 + tx] = __float2half(tile[tx][ty + j * 8]);
    }
}

// ---------------- LayerNorm ----------------
__global__ __launch_bounds__(256) void ln_kernel(const float* __restrict__ x,
                                                 const float* __restrict__ w,
                                                 const float* __restrict__ b,
                                                 float* __restrict__ y,
                                                 __half* __restrict__ yh)
{
    int row = blockIdx.x;
    int t = threadIdx.x;
    const float4* xr = (const float4*)(x + (size_t)row * D_MODEL);
    float4 v = xr[t];
    float s  = v.x + v.y + v.z + v.w;
    float sq = v.x*v.x + v.y*v.y + v.z*v.z + v.w*v.w;
    #pragma unroll
    for (int o = 16; o > 0; o >>= 1) {
        s  += __shfl_xor_sync(0xFFFFFFFFu, s, o);
        sq += __shfl_xor_sync(0xFFFFFFFFu, sq, o);
    }
    __shared__ float ss[8], ssq[8];
    int wid = t >> 5, lane = t & 31;
    if (lane == 0) { ss[wid] = s; ssq[wid] = sq; }
    __syncthreads();
    if (wid == 0) {
        s  = (lane < 8) ? ss[lane]  : 0.0f;
        sq = (lane < 8) ? ssq[lane] : 0.0f;
        #pragma unroll
        for (int o = 4; o > 0; o >>= 1) {
            s  += __shfl_xor_sync(0xFFFFFFFFu, s, o);
            sq += __shfl_xor_sync(0xFFFFFFFFu, sq, o);
        }
        if (lane == 0) {
            float mu = s * (1.0f / D_MODEL);
            ss[0]  = mu;
            ssq[0] = rsqrtf(sq * (1.0f / D_MODEL) - mu * mu + 1e-5f);
        }
    }
    __syncthreads();
    float mu = ss[0], rstd = ssq[0];
    float4 wv = ((const float4*)w)[t];
    float4 bv = ((const float4*)b)[t];
    float4 r;
    r.x = (v.x - mu) * rstd * wv.x + bv.x;
    r.y = (v.y - mu) * rstd * wv.y + bv.y;
    r.z = (v.z - mu) * rstd * wv.z + bv.z;
    r.w = (v.w - mu) * rstd * wv.w + bv.w;
    ((float4*)(y + (size_t)row * D_MODEL))[t] = r;
    __half2 h0 = __floats2half2_rn(r.x, r.y);
    __half2 h1 = __floats2half2_rn(r.z, r.w);
    uint2 u = { *(uint32_t*)&h0, *(uint32_t*)&h1 };
    *(uint2*)(yh + (size_t)row * D_MODEL + t * 4) = u;
}

// ---------------- MMA helpers ----------------
__device__ __forceinline__ void mma_f16(float* d, const uint32_t* a, const uint32_t* b) {
    asm volatile(
        "mma.sync.aligned.m16n8k16.row.col.f32.f16.f16.f32 "
        "{%0,%1,%2,%3}, {%4,%5,%6,%7}, {%8,%9}, {%0,%1,%2,%3};\n"
        : "+f"(d[0]), "+f"(d[1]), "+f"(d[2]), "+f"(d[3])
        : "r"(a[0]), "r"(a[1]), "r"(a[2]), "r"(a[3]), "r"(b[0]), "r"(b[1]));
}
__device__ __forceinline__ void mma_tf32(float* d, const uint32_t* a, const uint32_t* b) {
    asm volatile(
        "mma.sync.aligned.m16n8k8.row.col.f32.tf32.tf32.f32 "
        "{%0,%1,%2,%3}, {%4,%5,%6,%7}, {%8,%9}, {%0,%1,%2,%3};\n"
        : "+f"(d[0]), "+f"(d[1]), "+f"(d[2]), "+f"(d[3])
        : "r"(a[0]), "r"(a[1]), "r"(a[2]), "r"(a[3]), "r"(b[0]), "r"(b[1]));
}
__device__ __forceinline__ void ldsm_x4(uint32_t& r0, uint32_t& r1, uint32_t& r2, uint32_t& r3,
                                        uint32_t addr) {
    asm volatile("ldmatrix.sync.aligned.m8n8.x4.shared.b16 {%0,%1,%2,%3}, [%4];"
                 : "=r"(r0), "=r"(r1), "=r"(r2), "=r"(r3) : "r"(addr));
}
__device__ __forceinline__ void cp16(uint32_t dst, const void* src) {
    asm volatile("cp.async.cg.shared.global [%0], [%1], 16;\n" :: "r"(dst), "l"(src));
}
__device__ __forceinline__ void cp_commit() {
    asm volatile("cp.async.commit_group;\n");
}
template <int N>
__device__ __forceinline__ void cp_wait() {
    asm volatile("cp.async.wait_group %0;\n" :: "n"(N));
}

// ---------------- fp16 GEMM: BK=64, 3-stage cp.async, ldmatrix fragments ----------------
#define EPI_BIAS      0
#define EPI_BIAS_GELU 1
#define EPI_BIAS_RES  2

#define ROW_BYTES 144                    // 64 halves (128B) + 16B pad
#define STAGE_BYTES (128 * ROW_BYTES)    // per matrix per stage = 18432
#define GEMM_STAGES 3
#define GEMM_SMEM_BYTES (GEMM_STAGES * 2 * STAGE_BYTES)   // 110592

template <int EPI>
__global__ __launch_bounds__(256, 2) void mma_gemm(const __half* __restrict__ A,
                                                   const __half* __restrict__ Bt,
                                                   const float* __restrict__ bias,
                                                   const float* __restrict__ res,
                                                   void* __restrict__ Cv,
                                                   int M, int N, int K)
{
    extern __shared__ uint8_t smem8[];
    uint32_t sbA = (uint32_t)__cvta_generic_to_shared(smem8);
    uint32_t sbB = sbA + GEMM_STAGES * STAGE_BYTES;

    int tid = threadIdx.x;
    int wid = tid >> 5, lane = tid & 31;
    int gid = lane >> 2, tig = lane & 3;
    int warp_m = wid & 1, warp_n = wid >> 1;
    int bx = blockIdx.x, by = blockIdx.y;

    // cp.async coords: 4 x 16B per matrix per stage per thread
    const __half* Asrc[4];
    const __half* Bsrc[4];
    uint32_t Adst[4], Bdst[4];
    #pragma unroll
    for (int j = 0; j < 4; j++) {
        int q = tid + j * 256;
        int r = q >> 3, c = q & 7;          // row 0..127, 16B unit 0..7
        Asrc[j] = A  + (size_t)(by * 128 + r) * K + c * 8;
        Bsrc[j] = Bt + (size_t)(bx * 128 + r) * K + c * 8;
        Adst[j] = sbA + r * ROW_BYTES + c * 16;
        Bdst[j] = sbB + r * ROW_BYTES + c * 16;
    }

    // ldmatrix lane base addresses
    uint32_t a_lm = sbA + (warp_m * 64 + (lane & 15)) * ROW_BYTES + ((lane >> 4) * 16);
    uint32_t b_lm = sbB + (warp_n * 32 + (lane & 15)) * ROW_BYTES + ((lane >> 4) * 16);

    float acc[4][4][4];
    #pragma unroll
    for (int mt = 0; mt < 4; mt++)
        #pragma unroll
        for (int nt = 0; nt < 4; nt++)
            #pragma unroll
            for (int r = 0; r < 4; r++) acc[mt][nt][r] = 0.0f;

    int nIter = K >> 6;   // BK = 64
    #pragma unroll
    for (int s = 0; s < 2; s++) {
        #pragma unroll
        for (int j = 0; j < 4; j++) {
            cp16(Adst[j] + s * STAGE_BYTES, Asrc[j] + s * 64);
            cp16(Bdst[j] + s * STAGE_BYTES, Bsrc[j] + s * 64);
        }
        cp_commit();
    }

    for (int it = 0; it < nIter; it++) {
        if (it + 2 < nIter) {
            int sb = (it + 2) % GEMM_STAGES;
            int k0 = (it + 2) << 6;
            #pragma unroll
            for (int j = 0; j < 4; j++) {
                cp16(Adst[j] + sb * STAGE_BYTES, Asrc[j] + k0);
                cp16(Bdst[j] + sb * STAGE_BYTES, Bsrc[j] + k0);
            }
            cp_commit();
            cp_wait<2>();
        } else if (it + 1 < nIter) {
            cp_wait<1>();
        } else {
            cp_wait<0>();
        }
        __syncthreads();

        int buf = it % GEMM_STAGES;
        uint32_t abase = a_lm + buf * STAGE_BYTES;
        uint32_t bbase = b_lm + buf * STAGE_BYTES;
        #pragma unroll
        for (int ks = 0; ks < 4; ks++) {      // four k16 steps per 64-chunk
            uint32_t af[4][4], bf[4][2];
            #pragma unroll
            for (int mt = 0; mt < 4; mt++)
                ldsm_x4(af[mt][0], af[mt][1], af[mt][2], af[mt][3],
                        abase + mt * 16 * ROW_BYTES + ks * 32);
            #pragma unroll
            for (int p = 0; p < 2; p++)
                ldsm_x4(bf[2*p][0], bf[2*p+1][0], bf[2*p][1], bf[2*p+1][1],
                        bbase + p * 16 * ROW_BYTES + ks * 32);
            #pragma unroll
            for (int mt = 0; mt < 4; mt++)
                #pragma unroll
                for (int nt = 0; nt < 4; nt++)
                    mma_f16(acc[mt][nt], af[mt], bf[nt]);
        }
        __syncthreads();
    }

    // epilogue
    #pragma unroll
    for (int mt = 0; mt < 4; mt++) {
        #pragma unroll
        for (int nt = 0; nt < 4; nt++) {
            int row0 = by * 128 + warp_m * 64 + mt * 16 + gid;
            int col  = bx * 128 + warp_n * 32 + nt * 8 + tig * 2;
            float b0 = bias[col], b1 = bias[col + 1];
            #pragma unroll
            for (int half_i = 0; half_i < 2; half_i++) {
                int row = row0 + half_i * 8;
                float v0 = acc[mt][nt][half_i * 2 + 0] + b0;
                float v1 = acc[mt][nt][half_i * 2 + 1] + b1;
                if (EPI == EPI_BIAS_GELU) {
                    v0 = 0.5f * v0 * (1.0f + erff(v0 * 0.70710678118654752f));
                    v1 = 0.5f * v1 * (1.0f + erff(v1 * 0.70710678118654752f));
                    __half2 hv = __floats2half2_rn(v0, v1);
                    *(__half2*)((__half*)Cv + (size_t)row * N + col) = hv;
                } else {
                    if (EPI == EPI_BIAS_RES) {
                        float2 rv = *(const float2*)(res + (size_t)row * N + col);
                        v0 += rv.x; v1 += rv.y;
                    }
                    float2 o2 = { v0, v1 };
                    *(float2*)((float*)Cv + (size_t)row * N + col) = o2;
                }
            }
        }
    }
}

// ---------------- Flash attention on tensor cores (tf32 mma.sync) ----------------
#define QP_STRIDE 68
#define V_STRIDE  72
#define ATTN_SMEM ((2 * 64 * QP_STRIDE + 64 * V_STRIDE) * 4)

__global__ __launch_bounds__(128) void attn_kernel(const float* __restrict__ qkv,
                                                   __half* __restrict__ out)
{
    extern __shared__ uint32_t smem_a[];
    uint32_t* QP = smem_a;
    uint32_t* Ks = smem_a + 64 * QP_STRIDE;
    uint32_t* Vs = smem_a + 2 * 64 * QP_STRIDE;

    int bh = blockIdx.y;
    int b = bh >> 4, h = bh & 15;
    int q0 = blockIdx.x * 64;
    int tid = threadIdx.x;
    int wid = tid >> 5, lane = tid & 31;
    int gid = lane >> 2, tig = lane & 3;
    int m0 = wid * 16;

    for (int i = tid; i < 64 * 16; i += 128) {
        int r = i >> 4, c = (i & 15) * 4;
        float4 v = *(const float4*)(qkv + (size_t)(b * SEQ + q0 + r) * 3 * D_MODEL + h * HD + c);
        uint4 u = { f2tf32(v.x * 0.125f), f2tf32(v.y * 0.125f),
                    f2tf32(v.z * 0.125f), f2tf32(v.w * 0.125f) };
        *(uint4*)&QP[r * QP_STRIDE + c] = u;
    }
    __syncthreads();

    uint32_t qa[8][4];
    #pragma unroll
    for (int ks = 0; ks < 8; ks++) {
        int kk = ks * 8;
        qa[ks][0] = QP[(m0 + gid    ) * QP_STRIDE + kk + tig    ];
        qa[ks][1] = QP[(m0 + gid + 8) * QP_STRIDE + kk + tig    ];
        qa[ks][2] = QP[(m0 + gid    ) * QP_STRIDE + kk + tig + 4];
        qa[ks][3] = QP[(m0 + gid + 8) * QP_STRIDE + kk + tig + 4];
    }

    float o[8][4];
    #pragma unroll
    for (int nt = 0; nt < 8; nt++)
        #pragma unroll
        for (int j = 0; j < 4; j++) o[nt][j] = 0.0f;
    float ms0 = -3.0e38f, ms1 = -3.0e38f, ls0 = 0.0f, ls1 = 0.0f;

    __syncthreads();

    for (int kt = 0; kt <= q0; kt += 64) {
        for (int i = tid; i < 64 * 16; i += 128) {
            int r = i >> 4, c = (i & 15) * 4;
            const float* base = qkv + (size_t)(b * SEQ + kt + r) * 3 * D_MODEL + h * HD + c;
            float4 kv = *(const float4*)(base + D_MODEL);
            float4 vv = *(const float4*)(base + 2 * D_MODEL);
            uint4 uk = { f2tf32(kv.x), f2tf32(kv.y), f2tf32(kv.z), f2tf32(kv.w) };
            uint4 uv = { f2tf32(vv.x), f2tf32(vv.y), f2tf32(vv.z), f2tf32(vv.w) };
            *(uint4*)&Ks[r * QP_STRIDE + c] = uk;
            *(uint4*)&Vs[r * V_STRIDE  + c] = uv;
        }
        __syncthreads();

        float sc[8][4];
        #pragma unroll
        for (int nt = 0; nt < 8; nt++)
            #pragma unroll
            for (int j = 0; j < 4; j++) sc[nt][j] = 0.0f;
        #pragma unroll
        for (int ks = 0; ks < 8; ks++) {
            int kk = ks * 8;
            #pragma unroll
            for (int nt = 0; nt < 8; nt++) {
                uint32_t bf[2] = { Ks[(nt * 8 + gid) * QP_STRIDE + kk + tig],
                                   Ks[(nt * 8 + gid) * QP_STRIDE + kk + tig + 4] };
                mma_tf32(sc[nt], qa[ks], bf);
            }
        }

        if (kt == q0) {
            int r0 = m0 + gid, r1 = r0 + 8;
            #pragma unroll
            for (int nt = 0; nt < 8; nt++) {
                int c0 = nt * 8 + tig * 2;
                if (c0     > r0) sc[nt][0] = -3.0e38f;
                if (c0 + 1 > r0) sc[nt][1] = -3.0e38f;
                if (c0     > r1) sc[nt][2] = -3.0e38f;
                if (c0 + 1 > r1) sc[nt][3] = -3.0e38f;
            }
        }

        float tm0 = -3.0e38f, tm1 = -3.0e38f;
        #pragma unroll
        for (int nt = 0; nt < 8; nt++) {
            tm0 = fmaxf(tm0, fmaxf(sc[nt][0], sc[nt][1]));
            tm1 = fmaxf(tm1, fmaxf(sc[nt][2], sc[nt][3]));
        }
        #pragma unroll
        for (int off = 1; off <= 2; off <<= 1) {
            tm0 = fmaxf(tm0, __shfl_xor_sync(0xFFFFFFFFu, tm0, off));
            tm1 = fmaxf(tm1, __shfl_xor_sync(0xFFFFFFFFu, tm1, off));
        }
        float mn0 = fmaxf(ms0, tm0), mn1 = fmaxf(ms1, tm1);
        float cc0 = __expf(ms0 - mn0), cc1 = __expf(ms1 - mn1);
        ms0 = mn0; ms1 = mn1;
        float ps0 = 0.0f, ps1 = 0.0f;
        #pragma unroll
        for (int nt = 0; nt < 8; nt++) {
            sc[nt][0] = __expf(sc[nt][0] - mn0); ps0 += sc[nt][0];
            sc[nt][1] = __expf(sc[nt][1] - mn0); ps0 += sc[nt][1];
            sc[nt][2] = __expf(sc[nt][2] - mn1); ps1 += sc[nt][2];
            sc[nt][3] = __expf(sc[nt][3] - mn1); ps1 += sc[nt][3];
        }
        #pragma unroll
        for (int off = 1; off <= 2; off <<= 1) {
            ps0 += __shfl_xor_sync(0xFFFFFFFFu, ps0, off);
            ps1 += __shfl_xor_sync(0xFFFFFFFFu, ps1, off);
        }
        ls0 = ls0 * cc0 + ps0;
        ls1 = ls1 * cc1 + ps1;
        #pragma unroll
        for (int nt = 0; nt < 8; nt++) {
            o[nt][0] *= cc0; o[nt][1] *= cc0;
            o[nt][2] *= cc1; o[nt][3] *= cc1;
        }

        __syncwarp();
        #pragma unroll
        for (int nt = 0; nt < 8; nt++) {
            int c0 = nt * 8 + tig * 2;
            QP[(m0 + gid    ) * QP_STRIDE + c0    ] = f2tf32(sc[nt][0]);
            QP[(m0 + gid    ) * QP_STRIDE + c0 + 1] = f2tf32(sc[nt][1]);
            QP[(m0 + gid + 8) * QP_STRIDE + c0    ] = f2tf32(sc[nt][2]);
            QP[(m0 + gid + 8) * QP_STRIDE + c0 + 1] = f2tf32(sc[nt][3]);
        }
        __syncwarp();

        #pragma unroll
        for (int ks = 0; ks < 8; ks++) {
            int kk = ks * 8;
            uint32_t af[4] = { QP[(m0 + gid    ) * QP_STRIDE + kk + tig    ],
                               QP[(m0 + gid + 8) * QP_STRIDE + kk + tig    ],
                               QP[(m0 + gid    ) * QP_STRIDE + kk + tig + 4],
                               QP[(m0 + gid + 8) * QP_STRIDE + kk + tig + 4] };
            #pragma unroll
            for (int nt = 0; nt < 8; nt++) {
                uint32_t bf[2] = { Vs[(kk + tig    ) * V_STRIDE + nt * 8 + gid],
                                   Vs[(kk + tig + 4) * V_STRIDE + nt * 8 + gid] };
                mma_tf32(o[nt], af, bf);
            }
        }
        __syncthreads();
    }

    float inv0 = 1.0f / ls0, inv1 = 1.0f / ls1;
    int row0 = b * SEQ + q0 + m0 + gid;
    int row1 = row0 + 8;
    #pragma unroll
    for (int nt = 0; nt < 8; nt++) {
        int col = h * HD + nt * 8 + tig * 2;
        *(__half2*)(out + (size_t)row0 * D_MODEL + col) = __floats2half2_rn(o[nt][0] * inv0, o[nt][1] * inv0);
        *(__half2*)(out + (size_t)row1 * D_MODEL + col) = __floats2half2_rn(o[nt][2] * inv1, o[nt][3] * inv1);
    }
}

// ---------------- launch ----------------
extern "C" void kernel_launch(void* const* d_in, const int* in_sizes, int n_in,
                              void* d_out, int out_size)
{
    const float* x          = (const float*)d_in[0];
    const float* ln1_w      = (const float*)d_in[1];
    const float* ln1_b      = (const float*)d_in[2];
    const float* qkv_w      = (const float*)d_in[3];
    const float* qkv_b      = (const float*)d_in[4];
    const float* attn_out_w = (const float*)d_in[5];
    const float* attn_out_b = (const float*)d_in[6];
    const float* ln2_w      = (const float*)d_in[7];
    const float* ln2_b      = (const float*)d_in[8];
    const float* c_fc_w     = (const float*)d_in[9];
    const float* c_fc_b     = (const float*)d_in[10];
    const float* c_proj_w   = (const float*)d_in[11];
    const float* c_proj_b   = (const float*)d_in[12];
    float* out = (float*)d_out;

    float *XN, *QKV, *H, *HN;
    __half *XNh, *Oh, *HNh, *Gh, *Wqkv, *Wproj, *Wfc, *Wpr2;
    cudaGetSymbolAddress((void**)&XN,   g_XN);
    cudaGetSymbolAddress((void**)&XNh,  g_XNh);
    cudaGetSymbolAddress((void**)&QKV,  g_QKV);
    cudaGetSymbolAddress((void**)&Oh,   g_Oh);
    cudaGetSymbolAddress((void**)&H,    g_H);
    cudaGetSymbolAddress((void**)&HN,   g_HN);
    cudaGetSymbolAddress((void**)&HNh,  g_HNh);
    cudaGetSymbolAddress((void**)&Gh,   g_Gh);
    cudaGetSymbolAddress((void**)&Wqkv, g_Wqkv);
    cudaGetSymbolAddress((void**)&Wproj,g_Wproj);
    cudaGetSymbolAddress((void**)&Wfc,  g_Wfc);
    cudaGetSymbolAddress((void**)&Wpr2, g_Wpr2);

    cudaFuncSetAttribute(mma_gemm<EPI_BIAS>,      cudaFuncAttributeMaxDynamicSharedMemorySize, GEMM_SMEM_BYTES);
    cudaFuncSetAttribute(mma_gemm<EPI_BIAS_GELU>, cudaFuncAttributeMaxDynamicSharedMemorySize, GEMM_SMEM_BYTES);
    cudaFuncSetAttribute(mma_gemm<EPI_BIAS_RES>,  cudaFuncAttributeMaxDynamicSharedMemorySize, GEMM_SMEM_BYTES);
    cudaFuncSetAttribute(attn_kernel,             cudaFuncAttributeMaxDynamicSharedMemorySize, ATTN_SMEM);

    // weight transposes -> [N][K] fp16
    cvt_t_kernel<<<dim3(3 * D_MODEL / 32, D_MODEL / 32), 256>>>(qkv_w, Wqkv, D_MODEL, 3 * D_MODEL);
    cvt_t_kernel<<<dim3(D_MODEL / 32, D_MODEL / 32), 256>>>(attn_out_w, Wproj, D_MODEL, D_MODEL);
    cvt_t_kernel<<<dim3(4 * D_MODEL / 32, D_MODEL / 32), 256>>>(c_fc_w, Wfc, D_MODEL, 4 * D_MODEL);
    cvt_t_kernel<<<dim3(D_MODEL / 32, 4 * D_MODEL / 32), 256>>>(c_proj_w, Wpr2, 4 * D_MODEL, D_MODEL);

    ln_kernel<<<ROWS, 256>>>(x, ln1_w, ln1_b, XN, XNh);

    mma_gemm<EPI_BIAS><<<dim3(3 * D_MODEL / 128, ROWS / 128), 256, GEMM_SMEM_BYTES>>>(
        XNh, Wqkv, qkv_b, nullptr, QKV, ROWS, 3 * D_MODEL, D_MODEL);

    attn_kernel<<<dim3(SEQ / 64, BATCH * NHEAD), 128, ATTN_SMEM>>>(QKV, Oh);

    mma_gemm<EPI_BIAS_RES><<<dim3(D_MODEL / 128, ROWS / 128), 256, GEMM_SMEM_BYTES>>>(
        Oh, Wproj, attn_out_b, XN, H, ROWS, D_MODEL, D_MODEL);

    ln_kernel<<<ROWS, 256>>>(H, ln2_w, ln2_b, HN, HNh);

    mma_gemm<EPI_BIAS_GELU><<<dim3(4 * D_MODEL / 128, ROWS / 128), 256, GEMM_SMEM_BYTES>>>(
        HNh, Wfc, c_fc_b, nullptr, Gh, ROWS, 4 * D_MODEL, D_MODEL);

    mma_gemm<EPI_BIAS_RES><<<dim3(D_MODEL / 128, ROWS / 128), 256, GEMM_SMEM_BYTES>>>(
        Gh, Wpr2, c_proj_b, HN, out, ROWS, D_MODEL, 4 * D_MODEL);
}

// round 10
// speedup vs baseline: 6.8038x; 1.1635x over previous
#include <cuda_runtime.h>
#include <cuda_fp16.h>
#include <math.h>
#include <stdint.h>

#define D_MODEL 1024
#define SEQ 2048
#define BATCH 2
#define NHEAD 16
#define HD 64
#define ROWS (BATCH*SEQ)   // 4096

// ---------------- scratch ----------------
__device__ float  g_XN [ROWS * D_MODEL];
__device__ __half g_XNh[ROWS * D_MODEL];
__device__ float  g_QKV[ROWS * 3 * D_MODEL];
__device__ __half g_Oh [ROWS * D_MODEL];
__device__ float  g_H  [ROWS * D_MODEL];
__device__ float  g_HN [ROWS * D_MODEL];
__device__ __half g_HNh[ROWS * D_MODEL];
__device__ __half g_Gh [ROWS * 4 * D_MODEL];
__device__ __half g_Wqkv [3 * D_MODEL * D_MODEL];
__device__ __half g_Wproj[D_MODEL * D_MODEL];
__device__ __half g_Wfc  [4 * D_MODEL * D_MODEL];
__device__ __half g_Wpr2 [D_MODEL * 4 * D_MODEL];

// ---------------- weight -> fp16 transpose ----------------
__global__ __launch_bounds__(256) void cvt_t_kernel(const float* __restrict__ W,
                                                    __half* __restrict__ Wt,
                                                    int K, int N)
{
    __shared__ float tile[32][33];
    int n0 = blockIdx.x * 32, k0 = blockIdx.y * 32;
    int tx = threadIdx.x & 31, ty = threadIdx.x >> 5;
    #pragma unroll
    for (int j = 0; j < 4; j++) {
        int k = k0 + ty + j * 8;
        tile[ty + j * 8][tx] = W[(size_t)k * N + n0 + tx];
    }
    __syncthreads();
    #pragma unroll
    for (int j = 0; j < 4; j++) {
        int n = n0 + ty + j * 8;
        Wt[(size_t)n * K + k0 + tx] = __float2half(tile[tx][ty + j * 8]);
    }
}

// ---------------- LayerNorm ----------------
__global__ __launch_bounds__(256) void ln_kernel(const float* __restrict__ x,
                                                 const float* __restrict__ w,
                                                 const float* __restrict__ b,
                                                 float* __restrict__ y,
                                                 __half* __restrict__ yh)
{
    int row = blockIdx.x;
    int t = threadIdx.x;
    const float4* xr = (const float4*)(x + (size_t)row * D_MODEL);
    float4 v = xr[t];
    float s  = v.x + v.y + v.z + v.w;
    float sq = v.x*v.x + v.y*v.y + v.z*v.z + v.w*v.w;
    #pragma unroll
    for (int o = 16; o > 0; o >>= 1) {
        s  += __shfl_xor_sync(0xFFFFFFFFu, s, o);
        sq += __shfl_xor_sync(0xFFFFFFFFu, sq, o);
    }
    __shared__ float ss[8], ssq[8];
    int wid = t >> 5, lane = t & 31;
    if (lane == 0) { ss[wid] = s; ssq[wid] = sq; }
    __syncthreads();
    if (wid == 0) {
        s  = (lane < 8) ? ss[lane]  : 0.0f;
        sq = (lane < 8) ? ssq[lane] : 0.0f;
        #pragma unroll
        for (int o = 4; o > 0; o >>= 1) {
            s  += __shfl_xor_sync(0xFFFFFFFFu, s, o);
            sq += __shfl_xor_sync(0xFFFFFFFFu, sq, o);
        }
        if (lane == 0) {
            float mu = s * (1.0f / D_MODEL);
            ss[0]  = mu;
            ssq[0] = rsqrtf(sq * (1.0f / D_MODEL) - mu * mu + 1e-5f);
        }
    }
    __syncthreads();
    float mu = ss[0], rstd = ssq[0];
    float4 wv = ((const float4*)w)[t];
    float4 bv = ((const float4*)b)[t];
    float4 r;
    r.x = (v.x - mu) * rstd * wv.x + bv.x;
    r.y = (v.y - mu) * rstd * wv.y + bv.y;
    r.z = (v.z - mu) * rstd * wv.z + bv.z;
    r.w = (v.w - mu) * rstd * wv.w + bv.w;
    ((float4*)(y + (size_t)row * D_MODEL))[t] = r;
    __half2 h0 = __floats2half2_rn(r.x, r.y);
    __half2 h1 = __floats2half2_rn(r.z, r.w);
    uint2 u = { *(uint32_t*)&h0, *(uint32_t*)&h1 };
    *(uint2*)(yh + (size_t)row * D_MODEL + t * 4) = u;
}

// ---------------- MMA helpers ----------------
__device__ __forceinline__ void mma_f16(float* d, const uint32_t* a, const uint32_t* b) {
    asm volatile(
        "mma.sync.aligned.m16n8k16.row.col.f32.f16.f16.f32 "
        "{%0,%1,%2,%3}, {%4,%5,%6,%7}, {%8,%9}, {%0,%1,%2,%3};\n"
        : "+f"(d[0]), "+f"(d[1]), "+f"(d[2]), "+f"(d[3])
        : "r"(a[0]), "r"(a[1]), "r"(a[2]), "r"(a[3]), "r"(b[0]), "r"(b[1]));
}
__device__ __forceinline__ void ldsm_x4(uint32_t& r0, uint32_t& r1, uint32_t& r2, uint32_t& r3,
                                        uint32_t addr) {
    asm volatile("ldmatrix.sync.aligned.m8n8.x4.shared.b16 {%0,%1,%2,%3}, [%4];"
                 : "=r"(r0), "=r"(r1), "=r"(r2), "=r"(r3) : "r"(addr));
}
__device__ __forceinline__ void ldsm_x4_t(uint32_t& r0, uint32_t& r1, uint32_t& r2, uint32_t& r3,
                                          uint32_t addr) {
    asm volatile("ldmatrix.sync.aligned.m8n8.x4.trans.shared.b16 {%0,%1,%2,%3}, [%4];"
                 : "=r"(r0), "=r"(r1), "=r"(r2), "=r"(r3) : "r"(addr));
}
__device__ __forceinline__ void cp16(uint32_t dst, const void* src) {
    asm volatile("cp.async.cg.shared.global [%0], [%1], 16;\n" :: "r"(dst), "l"(src));
}
__device__ __forceinline__ void cp_commit() {
    asm volatile("cp.async.commit_group;\n");
}
template <int N>
__device__ __forceinline__ void cp_wait() {
    asm volatile("cp.async.wait_group %0;\n" :: "n"(N));
}

// ---------------- fp16 GEMM: BK=64, 3-stage cp.async, ONE sync per iter ----------------
#define EPI_BIAS      0
#define EPI_BIAS_GELU 1
#define EPI_BIAS_RES  2

#define ROW_BYTES 144
#define STAGE_BYTES (128 * ROW_BYTES)
#define GEMM_STAGES 3
#define GEMM_SMEM_BYTES (GEMM_STAGES * 2 * STAGE_BYTES)   // 110592

template <int EPI>
__global__ __launch_bounds__(256, 2) void mma_gemm(const __half* __restrict__ A,
                                                   const __half* __restrict__ Bt,
                                                   const float* __restrict__ bias,
                                                   const float* __restrict__ res,
                                                   void* __restrict__ Cv,
                                                   int M, int N, int K)
{
    extern __shared__ uint8_t smem8[];
    uint32_t sbA = (uint32_t)__cvta_generic_to_shared(smem8);
    uint32_t sbB = sbA + GEMM_STAGES * STAGE_BYTES;

    int tid = threadIdx.x;
    int wid = tid >> 5, lane = tid & 31;
    int gid = lane >> 2, tig = lane & 3;
    int warp_m = wid & 1, warp_n = wid >> 1;
    int bx = blockIdx.x, by = blockIdx.y;

    const __half* Asrc[4];
    const __half* Bsrc[4];
    uint32_t Adst[4], Bdst[4];
    #pragma unroll
    for (int j = 0; j < 4; j++) {
        int q = tid + j * 256;
        int r = q >> 3, c = q & 7;
        Asrc[j] = A  + (size_t)(by * 128 + r) * K + c * 8;
        Bsrc[j] = Bt + (size_t)(bx * 128 + r) * K + c * 8;
        Adst[j] = sbA + r * ROW_BYTES + c * 16;
        Bdst[j] = sbB + r * ROW_BYTES + c * 16;
    }

    uint32_t a_lm = sbA + (warp_m * 64 + (lane & 15)) * ROW_BYTES + ((lane >> 4) * 16);
    uint32_t b_lm = sbB + (warp_n * 32 + (lane & 15)) * ROW_BYTES + ((lane >> 4) * 16);

    float acc[4][4][4];
    #pragma unroll
    for (int mt = 0; mt < 4; mt++)
        #pragma unroll
        for (int nt = 0; nt < 4; nt++)
            #pragma unroll
            for (int r = 0; r < 4; r++) acc[mt][nt][r] = 0.0f;

    int nIter = K >> 6;
    #pragma unroll
    for (int s = 0; s < 2; s++) {
        #pragma unroll
        for (int j = 0; j < 4; j++) {
            cp16(Adst[j] + s * STAGE_BYTES, Asrc[j] + s * 64);
            cp16(Bdst[j] + s * STAGE_BYTES, Bsrc[j] + s * 64);
        }
        cp_commit();
    }

    for (int it = 0; it < nIter; it++) {
        cp_wait<1>();            // oldest pending group (stage it) complete
        __syncthreads();         // publish to all warps; bounds skew to <1 iter
        if (it + 2 < nIter) {    // safe: all warps finished compute(it-1)
            int sb = (it + 2) % GEMM_STAGES;
            int k0 = (it + 2) << 6;
            #pragma unroll
            for (int j = 0; j < 4; j++) {
                cp16(Adst[j] + sb * STAGE_BYTES, Asrc[j] + k0);
                cp16(Bdst[j] + sb * STAGE_BYTES, Bsrc[j] + k0);
            }
        }
        cp_commit();             // always commit (possibly empty) to keep counts

        int buf = it % GEMM_STAGES;
        uint32_t abase = a_lm + buf * STAGE_BYTES;
        uint32_t bbase = b_lm + buf * STAGE_BYTES;
        #pragma unroll
        for (int ks = 0; ks < 4; ks++) {
            uint32_t af[4][4], bf[4][2];
            #pragma unroll
            for (int mt = 0; mt < 4; mt++)
                ldsm_x4(af[mt][0], af[mt][1], af[mt][2], af[mt][3],
                        abase + mt * 16 * ROW_BYTES + ks * 32);
            #pragma unroll
            for (int p = 0; p < 2; p++)
                ldsm_x4(bf[2*p][0], bf[2*p+1][0], bf[2*p][1], bf[2*p+1][1],
                        bbase + p * 16 * ROW_BYTES + ks * 32);
            #pragma unroll
            for (int mt = 0; mt < 4; mt++)
                #pragma unroll
                for (int nt = 0; nt < 4; nt++)
                    mma_f16(acc[mt][nt], af[mt], bf[nt]);
        }
    }

    #pragma unroll
    for (int mt = 0; mt < 4; mt++) {
        #pragma unroll
        for (int nt = 0; nt < 4; nt++) {
            int row0 = by * 128 + warp_m * 64 + mt * 16 + gid;
            int col  = bx * 128 + warp_n * 32 + nt * 8 + tig * 2;
            float b0 = bias[col], b1 = bias[col + 1];
            #pragma unroll
            for (int half_i = 0; half_i < 2; half_i++) {
                int row = row0 + half_i * 8;
                float v0 = acc[mt][nt][half_i * 2 + 0] + b0;
                float v1 = acc[mt][nt][half_i * 2 + 1] + b1;
                if (EPI == EPI_BIAS_GELU) {
                    v0 = 0.5f * v0 * (1.0f + erff(v0 * 0.70710678118654752f));
                    v1 = 0.5f * v1 * (1.0f + erff(v1 * 0.70710678118654752f));
                    __half2 hv = __floats2half2_rn(v0, v1);
                    *(__half2*)((__half*)Cv + (size_t)row * N + col) = hv;
                } else {
                    if (EPI == EPI_BIAS_RES) {
                        float2 rv = *(const float2*)(res + (size_t)row * N + col);
                        v0 += rv.x; v1 += rv.y;
                    }
                    float2 o2 = { v0, v1 };
                    *(float2*)((float*)Cv + (size_t)row * N + col) = o2;
                }
            }
        }
    }
}

// ---------------- Flash attention: fp16 MMA + ldmatrix ----------------
// 128 thr = 4 warps, 64 queries (16/warp), 64-key tiles. Q/K/P non-trans
// ldmatrix (same pattern as GEMM); V via ldmatrix.x4.trans. fp32 softmax.
#define AROW 144                             // 64 halves + 16B pad
#define ATTN_SMEM (3 * 64 * AROW)            // QP | K | V = 27648 B

__global__ __launch_bounds__(128) void attn_kernel(const float* __restrict__ qkv,
                                                   __half* __restrict__ out)
{
    extern __shared__ uint8_t smem8[];
    uint32_t sb = (uint32_t)__cvta_generic_to_shared(smem8);
    uint8_t* QP = smem8;
    uint8_t* Ks = smem8 + 64 * AROW;
    uint8_t* Vs = smem8 + 2 * 64 * AROW;
    uint32_t sbQP = sb, sbK = sb + 64 * AROW, sbV = sb + 2 * 64 * AROW;

    int bh = blockIdx.y;
    int b = bh >> 4, h = bh & 15;
    int q0 = blockIdx.x * 64;
    int tid = threadIdx.x;
    int wid = tid >> 5, lane = tid & 31;
    int gid = lane >> 2, tig = lane & 3;
    int m0 = wid * 16;

    // load Q (scaled, fp16)
    for (int i = tid; i < 64 * 16; i += 128) {
        int r = i >> 4, c = (i & 15) * 4;
        float4 v = *(const float4*)(qkv + (size_t)(b * SEQ + q0 + r) * 3 * D_MODEL + h * HD + c);
        __half2 h0 = __floats2half2_rn(v.x * 0.125f, v.y * 0.125f);
        __half2 h1 = __floats2half2_rn(v.z * 0.125f, v.w * 0.125f);
        uint2 u = { *(uint32_t*)&h0, *(uint32_t*)&h1 };
        *(uint2*)(QP + r * AROW + c * 2) = u;
    }
    __syncthreads();

    // Q fragments -> regs (A operand, 4 k16 steps)
    uint32_t q_lm = sbQP + (m0 + (lane & 15)) * AROW + ((lane >> 4) * 16);
    uint32_t qa[4][4];
    #pragma unroll
    for (int ks = 0; ks < 4; ks++)
        ldsm_x4(qa[ks][0], qa[ks][1], qa[ks][2], qa[ks][3], q_lm + ks * 32);
    __syncthreads();   // Q reads done before QP reused as P

    uint32_t k_lm = sbK + ((lane & 15)) * AROW + ((lane >> 4) * 16);
    uint32_t p_lm = q_lm;   // P reuses QP rows (warp-private)

    float o[8][4];
    #pragma unroll
    for (int nt = 0; nt < 8; nt++)
        #pragma unroll
        for (int j = 0; j < 4; j++) o[nt][j] = 0.0f;
    float ms0 = -3.0e38f, ms1 = -3.0e38f, ls0 = 0.0f, ls1 = 0.0f;

    for (int kt = 0; kt <= q0; kt += 64) {
        // load K, V (fp16)
        for (int i = tid; i < 64 * 16; i += 128) {
            int r = i >> 4, c = (i & 15) * 4;
            const float* base = qkv + (size_t)(b * SEQ + kt + r) * 3 * D_MODEL + h * HD + c;
            float4 kv = *(const float4*)(base + D_MODEL);
            float4 vv = *(const float4*)(base + 2 * D_MODEL);
            __half2 k0h = __floats2half2_rn(kv.x, kv.y);
            __half2 k1h = __floats2half2_rn(kv.z, kv.w);
            __half2 v0h = __floats2half2_rn(vv.x, vv.y);
            __half2 v1h = __floats2half2_rn(vv.z, vv.w);
            uint2 uk = { *(uint32_t*)&k0h, *(uint32_t*)&k1h };
            uint2 uv = { *(uint32_t*)&v0h, *(uint32_t*)&v1h };
            *(uint2*)(Ks + r * AROW + c * 2) = uk;
            *(uint2*)(Vs + r * AROW + c * 2) = uv;
        }
        __syncthreads();

        // S = Q @ K^T : 4 k16 steps x 8 n-tiles
        float sc[8][4];
        #pragma unroll
        for (int nt = 0; nt < 8; nt++)
            #pragma unroll
            for (int j = 0; j < 4; j++) sc[nt][j] = 0.0f;
        #pragma unroll
        for (int ks = 0; ks < 4; ks++) {
            uint32_t bf[8][2];
            #pragma unroll
            for (int p = 0; p < 4; p++)
                ldsm_x4(bf[2*p][0], bf[2*p+1][0], bf[2*p][1], bf[2*p+1][1],
                        k_lm + p * 16 * AROW + ks * 32);
            #pragma unroll
            for (int nt = 0; nt < 8; nt++)
                mma_f16(sc[nt], qa[ks], bf[nt]);
        }

        // causal mask (diagonal tile)
        if (kt == q0) {
            int r0 = m0 + gid, r1 = r0 + 8;
            #pragma unroll
            for (int nt = 0; nt < 8; nt++) {
                int c0 = nt * 8 + tig * 2;
                if (c0     > r0) sc[nt][0] = -3.0e38f;
                if (c0 + 1 > r0) sc[nt][1] = -3.0e38f;
                if (c0     > r1) sc[nt][2] = -3.0e38f;
                if (c0 + 1 > r1) sc[nt][3] = -3.0e38f;
            }
        }

        // online softmax
        float tm0 = -3.0e38f, tm1 = -3.0e38f;
        #pragma unroll
        for (int nt = 0; nt < 8; nt++) {
            tm0 = fmaxf(tm0, fmaxf(sc[nt][0], sc[nt][1]));
            tm1 = fmaxf(tm1, fmaxf(sc[nt][2], sc[nt][3]));
        }
        #pragma unroll
        for (int off = 1; off <= 2; off <<= 1) {
            tm0 = fmaxf(tm0, __shfl_xor_sync(0xFFFFFFFFu, tm0, off));
            tm1 = fmaxf(tm1, __shfl_xor_sync(0xFFFFFFFFu, tm1, off));
        }
        float mn0 = fmaxf(ms0, tm0), mn1 = fmaxf(ms1, tm1);
        float cc0 = __expf(ms0 - mn0), cc1 = __expf(ms1 - mn1);
        ms0 = mn0; ms1 = mn1;
        float ps0 = 0.0f, ps1 = 0.0f;
        #pragma unroll
        for (int nt = 0; nt < 8; nt++) {
            sc[nt][0] = __expf(sc[nt][0] - mn0); ps0 += sc[nt][0];
            sc[nt][1] = __expf(sc[nt][1] - mn0); ps0 += sc[nt][1];
            sc[nt][2] = __expf(sc[nt][2] - mn1); ps1 += sc[nt][2];
            sc[nt][3] = __expf(sc[nt][3] - mn1); ps1 += sc[nt][3];
        }
        #pragma unroll
        for (int off = 1; off <= 2; off <<= 1) {
            ps0 += __shfl_xor_sync(0xFFFFFFFFu, ps0, off);
            ps1 += __shfl_xor_sync(0xFFFFFFFFu, ps1, off);
        }
        ls0 = ls0 * cc0 + ps0;
        ls1 = ls1 * cc1 + ps1;
        #pragma unroll
        for (int nt = 0; nt < 8; nt++) {
            o[nt][0] *= cc0; o[nt][1] *= cc0;
            o[nt][2] *= cc1; o[nt][3] *= cc1;
        }

        // P -> smem fp16 (warp-private rows of QP)
        __syncwarp();
        #pragma unroll
        for (int nt = 0; nt < 8; nt++) {
            int c0 = nt * 8 + tig * 2;
            __half2 p0 = __floats2half2_rn(sc[nt][0], sc[nt][1]);
            __half2 p1 = __floats2half2_rn(sc[nt][2], sc[nt][3]);
            *(__half2*)(QP + (m0 + gid    ) * AROW + c0 * 2) = p0;
            *(__half2*)(QP + (m0 + gid + 8) * AROW + c0 * 2) = p1;
        }
        __syncwarp();

        // O += P @ V : keys in 4 k16 steps; V via trans ldmatrix
        #pragma unroll
        for (int ks = 0; ks < 4; ks++) {
            uint32_t pf[4];
            ldsm_x4(pf[0], pf[1], pf[2], pf[3], p_lm + ks * 32);
            // V rows ks*16 + lane%16, col group (p*16 + (lane/16)*8) halves
            uint32_t v_base = sbV + (ks * 16 + (lane & 15)) * AROW + ((lane >> 4) * 16);
            #pragma unroll
            for (int p = 0; p < 4; p++) {
                uint32_t bf[2][2];
                ldsm_x4_t(bf[0][0], bf[0][1], bf[1][0], bf[1][1], v_base + p * 32);
                mma_f16(o[2*p    ], pf, bf[0]);
                mma_f16(o[2*p + 1], pf, bf[1]);
            }
        }
        __syncthreads();
    }

    float inv0 = 1.0f / ls0, inv1 = 1.0f / ls1;
    int row0 = b * SEQ + q0 + m0 + gid;
    int row1 = row0 + 8;
    #pragma unroll
    for (int nt = 0; nt < 8; nt++) {
        int col = h * HD + nt * 8 + tig * 2;
        *(__half2*)(out + (size_t)row0 * D_MODEL + col) = __floats2half2_rn(o[nt][0] * inv0, o[nt][1] * inv0);
        *(__half2*)(out + (size_t)row1 * D_MODEL + col) = __floats2half2_rn(o[nt][2] * inv1, o[nt][3] * inv1);
    }
}

// ---------------- launch ----------------
extern "C" void kernel_launch(void* const* d_in, const int* in_sizes, int n_in,
                              void* d_out, int out_size)
{
    const float* x          = (const float*)d_in[0];
    const float* ln1_w      = (const float*)d_in[1];
    const float* ln1_b      = (const float*)d_in[2];
    const float* qkv_w      = (const float*)d_in[3];
    const float* qkv_b      = (const float*)d_in[4];
    const float* attn_out_w = (const float*)d_in[5];
    const float* attn_out_b = (const float*)d_in[6];
    const float* ln2_w      = (const float*)d_in[7];
    const float* ln2_b      = (const float*)d_in[8];
    const float* c_fc_w     = (const float*)d_in[9];
    const float* c_fc_b     = (const float*)d_in[10];
    const float* c_proj_w   = (const float*)d_in[11];
    const float* c_proj_b   = (const float*)d_in[12];
    float* out = (float*)d_out;

    float *XN, *QKV, *H, *HN;
    __half *XNh, *Oh, *HNh, *Gh, *Wqkv, *Wproj, *Wfc, *Wpr2;
    cudaGetSymbolAddress((void**)&XN,   g_XN);
    cudaGetSymbolAddress((void**)&XNh,  g_XNh);
    cudaGetSymbolAddress((void**)&QKV,  g_QKV);
    cudaGetSymbolAddress((void**)&Oh,   g_Oh);
    cudaGetSymbolAddress((void**)&H,    g_H);
    cudaGetSymbolAddress((void**)&HN,   g_HN);
    cudaGetSymbolAddress((void**)&HNh,  g_HNh);
    cudaGetSymbolAddress((void**)&Gh,   g_Gh);
    cudaGetSymbolAddress((void**)&Wqkv, g_Wqkv);
    cudaGetSymbolAddress((void**)&Wproj,g_Wproj);
    cudaGetSymbolAddress((void**)&Wfc,  g_Wfc);
    cudaGetSymbolAddress((void**)&Wpr2, g_Wpr2);

    cudaFuncSetAttribute(mma_gemm<EPI_BIAS>,      cudaFuncAttributeMaxDynamicSharedMemorySize, GEMM_SMEM_BYTES);
    cudaFuncSetAttribute(mma_gemm<EPI_BIAS_GELU>, cudaFuncAttributeMaxDynamicSharedMemorySize, GEMM_SMEM_BYTES);
    cudaFuncSetAttribute(mma_gemm<EPI_BIAS_RES>,  cudaFuncAttributeMaxDynamicSharedMemorySize, GEMM_SMEM_BYTES);
    cudaFuncSetAttribute(attn_kernel,             cudaFuncAttributeMaxDynamicSharedMemorySize, ATTN_SMEM);

    cvt_t_kernel<<<dim3(3 * D_MODEL / 32, D_MODEL / 32), 256>>>(qkv_w, Wqkv, D_MODEL, 3 * D_MODEL);
    cvt_t_kernel<<<dim3(D_MODEL / 32, D_MODEL / 32), 256>>>(attn_out_w, Wproj, D_MODEL, D_MODEL);
    cvt_t_kernel<<<dim3(4 * D_MODEL / 32, D_MODEL / 32), 256>>>(c_fc_w, Wfc, D_MODEL, 4 * D_MODEL);
    cvt_t_kernel<<<dim3(D_MODEL / 32, 4 * D_MODEL / 32), 256>>>(c_proj_w, Wpr2, 4 * D_MODEL, D_MODEL);

    ln_kernel<<<ROWS, 256>>>(x, ln1_w, ln1_b, XN, XNh);

    mma_gemm<EPI_BIAS><<<dim3(3 * D_MODEL / 128, ROWS / 128), 256, GEMM_SMEM_BYTES>>>(
        XNh, Wqkv, qkv_b, nullptr, QKV, ROWS, 3 * D_MODEL, D_MODEL);

    attn_kernel<<<dim3(SEQ / 64, BATCH * NHEAD), 128, ATTN_SMEM>>>(QKV, Oh);

    mma_gemm<EPI_BIAS_RES><<<dim3(D_MODEL / 128, ROWS / 128), 256, GEMM_SMEM_BYTES>>>(
        Oh, Wproj, attn_out_b, XN, H, ROWS, D_MODEL, D_MODEL);

    ln_kernel<<<ROWS, 256>>>(H, ln2_w, ln2_b, HN, HNh);

    mma_gemm<EPI_BIAS_GELU><<<dim3(4 * D_MODEL / 128, ROWS / 128), 256, GEMM_SMEM_BYTES>>>(
        HNh, Wfc, c_fc_b, nullptr, Gh, ROWS, 4 * D_MODEL, D_MODEL);

    mma_gemm<EPI_BIAS_RES><<<dim3(D_MODEL / 128, ROWS / 128), 256, GEMM_SMEM_BYTES>>>(
        Gh, Wpr2, c_proj_b, HN, out, ROWS, D_MODEL, 4 * D_MODEL);
}